// round 13
// baseline (speedup 1.0000x reference)
#include <cuda_runtime.h>
#include <cuda_bf16.h>
#include <cuda_fp16.h>
#include <math.h>
#include <stdint.h>

// Problem constants
#define BATCH 2
#define SEQ   2048
#define EMB   1024
#define NHEAD 16
#define HDIM  64
#define STRIDE_BLK 128
#define CKEEP 8

// Scratch (device globals; no runtime allocation allowed).
__device__ __nv_bfloat16 g_QKVH[(size_t)BATCH * SEQ * 3 * EMB];  // qkv hi plane (bf16)
__device__ __nv_bfloat16 g_QKVL[(size_t)BATCH * SEQ * 3 * EMB];  // qkv lo plane (bf16)
__device__ __nv_bfloat16 g_AH[(size_t)4096 * 1024];
__device__ __nv_bfloat16 g_AL[(size_t)4096 * 1024];
__device__ __nv_bfloat16 g_WH[(size_t)3072 * 1024];              // W^T hi [N][K]

// ---------------------------------------------------------------------------
// helpers
// ---------------------------------------------------------------------------
__device__ __forceinline__ uint32_t bf2_pack(__nv_bfloat16 a, __nv_bfloat16 b) {
    __nv_bfloat162 v(a, b);
    return *reinterpret_cast<uint32_t*>(&v);
}
__device__ __forceinline__ void split_pair(float x, float y, uint32_t& hi, uint32_t& lo) {
    __nv_bfloat16 hx = __float2bfloat16(x), hy = __float2bfloat16(y);
    __nv_bfloat16 lx = __float2bfloat16(x - __bfloat162float(hx));
    __nv_bfloat16 ly = __float2bfloat16(y - __bfloat162float(hy));
    hi = bf2_pack(hx, hy);
    lo = bf2_pack(lx, ly);
}
__device__ __forceinline__ uint32_t h2_pack(__half a, __half b) {
    __half2 v = __halves2half2(a, b);
    return *reinterpret_cast<uint32_t*>(&v);
}
__device__ __forceinline__ void split_pair_f16(float x, float y, uint32_t& hi, uint32_t& lo) {
    __half hx = __float2half_rn(x), hy = __float2half_rn(y);
    __half lx = __float2half_rn(x - __half2float(hx));
    __half ly = __float2half_rn(y - __half2float(hy));
    hi = h2_pack(hx, hy);
    lo = h2_pack(lx, ly);
}
__device__ __forceinline__ void ldsm4(uint32_t& r0, uint32_t& r1,
                                      uint32_t& r2, uint32_t& r3, uint32_t addr) {
    asm volatile("ldmatrix.sync.aligned.m8n8.x4.shared.b16 {%0,%1,%2,%3},[%4];"
                 : "=r"(r0), "=r"(r1), "=r"(r2), "=r"(r3) : "r"(addr));
}
__device__ __forceinline__ void mma_bf16(float* d, const uint32_t* a,
                                         const uint32_t* b) {
    asm volatile(
        "mma.sync.aligned.m16n8k16.row.col.f32.bf16.bf16.f32 "
        "{%0,%1,%2,%3},{%4,%5,%6,%7},{%8,%9},{%0,%1,%2,%3};"
        : "+f"(d[0]), "+f"(d[1]), "+f"(d[2]), "+f"(d[3])
        : "r"(a[0]), "r"(a[1]), "r"(a[2]), "r"(a[3]), "r"(b[0]), "r"(b[1]));
}
__device__ __forceinline__ void mma_f16(float* d, const uint32_t* a,
                                        const uint32_t* b) {
    asm volatile(
        "mma.sync.aligned.m16n8k16.row.col.f32.f16.f16.f32 "
        "{%0,%1,%2,%3},{%4,%5,%6,%7},{%8,%9},{%0,%1,%2,%3};"
        : "+f"(d[0]), "+f"(d[1]), "+f"(d[2]), "+f"(d[3])
        : "r"(a[0]), "r"(a[1]), "r"(a[2]), "r"(a[3]), "r"(b[0]), "r"(b[1]));
}
__device__ __forceinline__ uint32_t smem_u32(const void* p) {
    uint32_t a;
    asm("{.reg .u64 t; cvta.to.shared.u64 t, %1; cvt.u32.u64 %0, t;}" : "=r"(a) : "l"(p));
    return a;
}
__device__ __forceinline__ uint32_t prmt(uint32_t a, uint32_t b, uint32_t s) {
    uint32_t d;
    asm("prmt.b32 %0,%1,%2,%3;" : "=r"(d) : "r"(a), "r"(b), "r"(s));
    return d;
}
__device__ __forceinline__ void cp_async16(uint32_t smem_addr, const void* gptr) {
    asm volatile("cp.async.cg.shared.global [%0], [%1], 16;"
                 :: "r"(smem_addr), "l"(gptr) : "memory");
}
__device__ __forceinline__ void cp_commit() {
    asm volatile("cp.async.commit_group;" ::: "memory");
}
template <int N>
__device__ __forceinline__ void cp_wait() {
    asm volatile("cp.async.wait_group %0;" :: "n"(N) : "memory");
}

// ---------------------------------------------------------------------------
// fp32 -> fp16 hi/lo split, elementwise
// ---------------------------------------------------------------------------
__global__ __launch_bounds__(256) void conv_split_f16(
    const float* __restrict__ X, __half* __restrict__ Hi,
    __half* __restrict__ Lo, int n4)
{
    int i = blockIdx.x * blockDim.x + threadIdx.x;
    if (i >= n4) return;
    float4 v = reinterpret_cast<const float4*>(X)[i];
    uint32_t h0, l0, h1, l1;
    split_pair_f16(v.x, v.y, h0, l0);
    split_pair_f16(v.z, v.w, h1, l1);
    uint2 hh = {h0, h1}, ll = {l0, l1};
    reinterpret_cast<uint2*>(Hi)[i] = hh;
    reinterpret_cast<uint2*>(Lo)[i] = ll;
}

// ---------------------------------------------------------------------------
// fp32 [K][N] -> transposed fp16 hi-only [N][K]
// ---------------------------------------------------------------------------
__global__ __launch_bounds__(256) void conv_T_f16h(
    const float* __restrict__ W, __half* __restrict__ HiT, int K, int N)
{
    __shared__ float t[32][33];
    const int n0 = blockIdx.x * 32, k0 = blockIdx.y * 32;
    const int tx = threadIdx.x, ty = threadIdx.y;  // 32 x 8
    #pragma unroll
    for (int i = 0; i < 32; i += 8)
        t[ty + i][tx] = W[(size_t)(k0 + ty + i) * N + n0 + tx];
    __syncthreads();
    #pragma unroll
    for (int i = 0; i < 32; i += 8)
        HiT[(size_t)(n0 + ty + i) * K + k0 + tx] = __float2half_rn(t[tx][ty + i]);
}

// ---------------------------------------------------------------------------
// Shared tile geometry
// ---------------------------------------------------------------------------
#define GBM 128
#define GBN 128
#define GBK 32
#define ASTR 40
#define A_CH (GBM * ASTR)
#define B_CH (GBN * ASTR)

// ---------------------------------------------------------------------------
// fp16x2 GEMM with cp.async staging, 2 CTAs/SM:
// C = A @ Wt^T + bias, A = Ah+Al fp16 (exact), W = Wh fp16.
// Output fp32 (Cf32) or bf16 hi/lo planes (OH/OL).
// ---------------------------------------------------------------------------
#define F16_SMEM_BYTES ((4 * A_CH + 2 * B_CH) * 2)

__global__ __launch_bounds__(256, 2) void gemm_f16x2(
    const __half* __restrict__ Ah, const __half* __restrict__ Al,
    const __half* __restrict__ Bh,
    const float* __restrict__ bias, float* __restrict__ Cf32,
    __nv_bfloat16* __restrict__ OH, __nv_bfloat16* __restrict__ OL,
    int M, int N, int K)
{
    extern __shared__ __half smh[];
    uint32_t sbase = smem_u32(smh);

    const int tid  = threadIdx.x;
    const int lane = tid & 31;
    const int wid  = tid >> 5;
    const int wm   = wid >> 2;
    const int wn   = wid & 3;
    const int brow = blockIdx.y;
    const int bcol = blockIdx.x;

    const int lr = tid >> 2;
    const int lc = (tid & 3) * 8;

    const __half* Ah0 = Ah + (size_t)(brow * GBM + lr) * K + lc;
    const __half* Al0 = Al + (size_t)(brow * GBM + lr) * K + lc;
    const __half* Bh0 = Bh + (size_t)(bcol * GBN + lr) * K + lc;
    const size_t rstep = (size_t)64 * K;

    auto aoff = [](int buf, int part) { return (buf * 2 + part) * A_CH; };
    auto boff = [](int buf) { return 4 * A_CH + buf * B_CH; };

    const int so = lr * ASTR + lc;
    const uint32_t half_off = 64 * ASTR * 2;   // byte offset for rows +64

    auto stage = [&](int kt, int buf) {
        const int ko = kt * GBK;
        const uint32_t a0 = sbase + (uint32_t)(aoff(buf, 0) + so) * 2;
        const uint32_t a1 = sbase + (uint32_t)(aoff(buf, 1) + so) * 2;
        const uint32_t b0 = sbase + (uint32_t)(boff(buf) + so) * 2;
        cp_async16(a0,            Ah0 + ko);
        cp_async16(a0 + half_off, Ah0 + ko + rstep);
        cp_async16(a1,            Al0 + ko);
        cp_async16(a1 + half_off, Al0 + ko + rstep);
        cp_async16(b0,            Bh0 + ko);
        cp_async16(b0 + half_off, Bh0 + ko + rstep);
        cp_commit();
    };

    float acc[4][4][4] = {};

    const int nK = K / GBK;
    const int mat = lane >> 3;
    const int r8  = lane & 7;

    stage(0, 0);

    for (int kt = 0; kt < nK; kt++) {
        const int buf = kt & 1;
        if (kt + 1 < nK) {
            stage(kt + 1, buf ^ 1);
            cp_wait<1>();
        } else {
            cp_wait<0>();
        }
        __syncthreads();

        #pragma unroll
        for (int ks = 0; ks < 2; ks++) {
            uint32_t ah[4][4], al[4][4], bh[4][2];
            #pragma unroll
            for (int mi = 0; mi < 4; mi++) {
                const int row = wm * 64 + mi * 16 + (mat & 1) * 8 + r8;
                const int col = ks * 16 + (mat >> 1) * 8;
                const uint32_t a_addr = sbase + (uint32_t)(aoff(buf,0) + row * ASTR + col) * 2;
                ldsm4(ah[mi][0], ah[mi][1], ah[mi][2], ah[mi][3], a_addr);
                ldsm4(al[mi][0], al[mi][1], al[mi][2], al[mi][3], a_addr + A_CH * 2);
            }
            #pragma unroll
            for (int nt = 0; nt < 2; nt++) {
                const int row = wn * 32 + nt * 16 + (mat >> 1) * 8 + r8;
                const int col = ks * 16 + (mat & 1) * 8;
                const uint32_t b_addr = sbase + (uint32_t)(boff(buf) + row * ASTR + col) * 2;
                uint32_t r0, r1, r2, r3;
                ldsm4(r0, r1, r2, r3, b_addr);
                bh[2*nt][0] = r0; bh[2*nt][1] = r1; bh[2*nt+1][0] = r2; bh[2*nt+1][1] = r3;
            }
            #pragma unroll
            for (int mi = 0; mi < 4; mi++)
                #pragma unroll
                for (int nj = 0; nj < 4; nj++) {
                    mma_f16(acc[mi][nj], ah[mi], bh[nj]);
                    mma_f16(acc[mi][nj], al[mi], bh[nj]);
                }
        }
        __syncthreads();   // reads of buf done before next overwrite
    }

    #pragma unroll
    for (int nj = 0; nj < 4; nj++) {
        const int c = bcol * GBN + wn * 32 + nj * 8 + (lane & 3) * 2;
        const float2 bv = *reinterpret_cast<const float2*>(bias + c);
        #pragma unroll
        for (int mi = 0; mi < 4; mi++) {
            const int r0 = brow * GBM + wm * 64 + mi * 16 + (lane >> 2);
            float2 o0, o1;
            o0.x = acc[mi][nj][0] + bv.x;  o0.y = acc[mi][nj][1] + bv.y;
            o1.x = acc[mi][nj][2] + bv.x;  o1.y = acc[mi][nj][3] + bv.y;
            if (Cf32) {
                *reinterpret_cast<float2*>(Cf32 + (size_t)r0 * N + c)       = o0;
                *reinterpret_cast<float2*>(Cf32 + (size_t)(r0 + 8) * N + c) = o1;
            } else {
                uint32_t h0, l0, h1, l1;
                split_pair(o0.x, o0.y, h0, l0);
                split_pair(o1.x, o1.y, h1, l1);
                const size_t e0 = (size_t)r0 * N + c;
                const size_t e1 = (size_t)(r0 + 8) * N + c;
                *reinterpret_cast<uint32_t*>(OH + e0) = h0;
                *reinterpret_cast<uint32_t*>(OL + e0) = l0;
                *reinterpret_cast<uint32_t*>(OH + e1) = h1;
                *reinterpret_cast<uint32_t*>(OL + e1) = l1;
            }
        }
    }
}

// ---------------------------------------------------------------------------
// Tensor-core sparse-causal attention, register-resident P (R12 — 70us)
// ---------------------------------------------------------------------------
#define AT_VSTR 264
#define AT_QSTR 72
#define AT_KSTR 72
#define AT_VTH  0
#define AT_VTL  16896
#define AT_QH   33792
#define AT_QL   43008
#define AT_KH   52224
#define AT_KL   70656
#define AT_SMEM_BYTES (89088 * 2 + 256)

__device__ __forceinline__ int key_map(int j, int nstr, int qb) {
    return (j < nstr) ? ((j >> 3) << 7) + (STRIDE_BLK - CKEEP) + (j & 7)
                      : (qb << 7) + (j - nstr);
}

__global__ __launch_bounds__(256, 1) void attn_tc(
    const __nv_bfloat16* __restrict__ QKVH, const __nv_bfloat16* __restrict__ QKVL,
    __half* __restrict__ OH, __half* __restrict__ OL)
{
    const int qb  = 15 - blockIdx.x;
    const int h   = blockIdx.y;
    const int b   = blockIdx.z;
    const int tid = threadIdx.x;
    const int lane = tid & 31;
    const int wid  = tid >> 5;
    const int nstr = qb * CKEEP;
    const int cnt  = nstr + 128;
    const int gmax = (cnt + 15) >> 4;
    const int q0   = qb * 128;

    extern __shared__ __nv_bfloat16 sb16[];
    const uint32_t sbase = smem_u32(sb16);

    const size_t base = (size_t)b * SEQ * (3 * EMB);

    {
        const int row = tid >> 1;
        const int d0  = (tid & 1) * 32;
        const size_t g = base + (size_t)(q0 + row) * (3 * EMB) + h * HDIM + d0;
        const int eo = row * AT_QSTR + d0;
        #pragma unroll
        for (int i = 0; i < 4; i++) {
            *reinterpret_cast<uint4*>(sb16 + AT_QH + eo + i * 8) =
                *reinterpret_cast<const uint4*>(QKVH + g + i * 8);
            *reinterpret_cast<uint4*>(sb16 + AT_QL + eo + i * 8) =
                *reinterpret_cast<const uint4*>(QKVL + g + i * 8);
        }
    }

    {
        const int j = tid;
        if (j < cnt) {
            const int key = key_map(j, nstr, qb);
            const size_t g = base + (size_t)key * (3 * EMB) + EMB + h * HDIM;
            const int eo = j * AT_KSTR;
            #pragma unroll
            for (int i = 0; i < 8; i++) {
                *reinterpret_cast<uint4*>(sb16 + AT_KH + eo + i * 8) =
                    *reinterpret_cast<const uint4*>(QKVH + g + i * 8);
                *reinterpret_cast<uint4*>(sb16 + AT_KL + eo + i * 8) =
                    *reinterpret_cast<const uint4*>(QKVL + g + i * 8);
            }
        } else if (j < 16 * gmax) {
            const uint4 z = {0u, 0u, 0u, 0u};
            const int eo = j * AT_KSTR;
            #pragma unroll
            for (int i = 0; i < 8; i++) {
                *reinterpret_cast<uint4*>(sb16 + AT_KH + eo + i * 8) = z;
                *reinterpret_cast<uint4*>(sb16 + AT_KL + eo + i * 8) = z;
            }
        }
    }

    {
        const int p      = tid & 127;
        const bool lo_pl = tid >= 128;
        const int vtoff  = lo_pl ? AT_VTL : AT_VTH;
        const int k0     = 2 * p;
        if (k0 < cnt) {
            const __nv_bfloat16* plane = lo_pl ? QKVL : QKVH;
            const int keyA = key_map(k0, nstr, qb);
            const int keyB = key_map(k0 + 1, nstr, qb);
            const __nv_bfloat16* ra = plane + base + (size_t)keyA * (3 * EMB) + 2 * EMB + h * HDIM;
            const __nv_bfloat16* rb = plane + base + (size_t)keyB * (3 * EMB) + 2 * EMB + h * HDIM;
            #pragma unroll
            for (int i = 0; i < 8; i++) {
                uint4 a = *reinterpret_cast<const uint4*>(ra + i * 8);
                uint4 c = *reinterpret_cast<const uint4*>(rb + i * 8);
                const uint32_t aw[4] = {a.x, a.y, a.z, a.w};
                const uint32_t cw[4] = {c.x, c.y, c.z, c.w};
                #pragma unroll
                for (int e = 0; e < 4; e++) {
                    const int d = i * 8 + e * 2;
                    *reinterpret_cast<uint32_t*>(sb16 + vtoff + d * AT_VSTR + k0) =
                        prmt(aw[e], cw[e], 0x5410u);
                    *reinterpret_cast<uint32_t*>(sb16 + vtoff + (d + 1) * AT_VSTR + k0) =
                        prmt(aw[e], cw[e], 0x7632u);
                }
            }
        } else if (k0 < 16 * gmax) {
            #pragma unroll
            for (int d = 0; d < 64; d++)
                *reinterpret_cast<uint32_t*>(sb16 + vtoff + d * AT_VSTR + k0) = 0u;
        }
    }
    __syncthreads();

    const int mat = lane >> 3;
    const int r8  = lane & 7;

    float sacc[32][4];
    #pragma unroll
    for (int t = 0; t < 32; t++)
        #pragma unroll
        for (int e = 0; e < 4; e++) sacc[t][e] = 0.f;

    {
        const int arow = wid * 16 + (mat & 1) * 8 + r8;
        #pragma unroll
        for (int ks = 0; ks < 4; ks++) {
            uint32_t ah[4], al[4];
            const uint32_t aaddr = sbase + (uint32_t)(AT_QH + arow * AT_QSTR + ks * 16 + (mat >> 1) * 8) * 2;
            ldsm4(ah[0], ah[1], ah[2], ah[3], aaddr);
            ldsm4(al[0], al[1], al[2], al[3], aaddr + (AT_QL - AT_QH) * 2);
            #pragma unroll
            for (int g = 0; g < 16; g++) {
                if (g < gmax) {
                    const int brow = g * 16 + (mat >> 1) * 8 + r8;
                    const uint32_t baddr = sbase + (uint32_t)(AT_KH + brow * AT_KSTR + ks * 16 + (mat & 1) * 8) * 2;
                    uint32_t bh[2][2], bl[2][2];
                    uint32_t r0, r1, r2, r3;
                    ldsm4(r0, r1, r2, r3, baddr);
                    bh[0][0] = r0; bh[0][1] = r1; bh[1][0] = r2; bh[1][1] = r3;
                    ldsm4(r0, r1, r2, r3, baddr + (AT_KL - AT_KH) * 2);
                    bl[0][0] = r0; bl[0][1] = r1; bl[1][0] = r2; bl[1][1] = r3;
                    #pragma unroll
                    for (int half = 0; half < 2; half++) {
                        mma_bf16(sacc[2 * g + half], ah, bh[half]);
                        mma_bf16(sacc[2 * g + half], ah, bl[half]);
                        mma_bf16(sacc[2 * g + half], al, bh[half]);
                    }
                }
            }
        }
    }

    const int r0   = lane >> 2;
    const int c0   = (lane & 3) * 2;
    const int rowA = wid * 16 + r0;
    const int rowB = rowA + 8;
    const int limA = nstr + rowA;
    const int limB = nstr + rowB;
    const float scale = 0.125f;

    float mA = -1e30f, mB = -1e30f;
    #pragma unroll
    for (int t = 0; t < 32; t++) {
        if (t < 2 * gmax) {
            const int c = t * 8 + c0;
            sacc[t][0] = (c     <= limA) ? sacc[t][0] * scale : -1e30f;
            sacc[t][1] = (c + 1 <= limA) ? sacc[t][1] * scale : -1e30f;
            sacc[t][2] = (c     <= limB) ? sacc[t][2] * scale : -1e30f;
            sacc[t][3] = (c + 1 <= limB) ? sacc[t][3] * scale : -1e30f;
            mA = fmaxf(mA, fmaxf(sacc[t][0], sacc[t][1]));
            mB = fmaxf(mB, fmaxf(sacc[t][2], sacc[t][3]));
        }
    }
    mA = fmaxf(mA, __shfl_xor_sync(0xffffffffu, mA, 1));
    mA = fmaxf(mA, __shfl_xor_sync(0xffffffffu, mA, 2));
    mB = fmaxf(mB, __shfl_xor_sync(0xffffffffu, mB, 1));
    mB = fmaxf(mB, __shfl_xor_sync(0xffffffffu, mB, 2));

    float sA = 0.f, sB = 0.f;
    #pragma unroll
    for (int t = 0; t < 32; t++) {
        if (t < 2 * gmax) {
            sacc[t][0] = __expf(sacc[t][0] - mA);
            sacc[t][1] = __expf(sacc[t][1] - mA);
            sacc[t][2] = __expf(sacc[t][2] - mB);
            sacc[t][3] = __expf(sacc[t][3] - mB);
            sA += sacc[t][0] + sacc[t][1];
            sB += sacc[t][2] + sacc[t][3];
        }
    }
    sA += __shfl_xor_sync(0xffffffffu, sA, 1);
    sA += __shfl_xor_sync(0xffffffffu, sA, 2);
    sB += __shfl_xor_sync(0xffffffffu, sB, 1);
    sB += __shfl_xor_sync(0xffffffffu, sB, 2);

    float pacc[8][4];
    #pragma unroll
    for (int t = 0; t < 8; t++)
        #pragma unroll
        for (int e = 0; e < 4; e++) pacc[t][e] = 0.f;

    #pragma unroll
    for (int ks = 0; ks < 16; ks++) {
        if (ks < gmax) {
            uint32_t ah[4], al[4];
            split_pair(sacc[2*ks][0],   sacc[2*ks][1],   ah[0], al[0]);
            split_pair(sacc[2*ks][2],   sacc[2*ks][3],   ah[1], al[1]);
            split_pair(sacc[2*ks+1][0], sacc[2*ks+1][1], ah[2], al[2]);
            split_pair(sacc[2*ks+1][2], sacc[2*ks+1][3], ah[3], al[3]);
            #pragma unroll
            for (int g = 0; g < 4; g++) {
                const int vrow = g * 16 + (mat >> 1) * 8 + r8;
                const uint32_t baddr = sbase + (uint32_t)(AT_VTH + vrow * AT_VSTR + ks * 16 + (mat & 1) * 8) * 2;
                uint32_t bh[2][2], bl[2][2];
                uint32_t r0_, r1_, r2_, r3_;
                ldsm4(r0_, r1_, r2_, r3_, baddr);
                bh[0][0] = r0_; bh[0][1] = r1_; bh[1][0] = r2_; bh[1][1] = r3_;
                ldsm4(r0_, r1_, r2_, r3_, baddr + (AT_VTL - AT_VTH) * 2);
                bl[0][0] = r0_; bl[0][1] = r1_; bl[1][0] = r2_; bl[1][1] = r3_;
                #pragma unroll
                for (int half = 0; half < 2; half++) {
                    mma_bf16(pacc[2 * g + half], ah, bh[half]);
                    mma_bf16(pacc[2 * g + half], ah, bl[half]);
                    mma_bf16(pacc[2 * g + half], al, bh[half]);
                }
            }
        }
    }

    {
        const float invA = 1.0f / sA;
        const float invB = 1.0f / sB;
        const size_t oA = (size_t)(b * SEQ + q0 + rowA) * EMB + h * HDIM;
        const size_t oB = (size_t)(b * SEQ + q0 + rowB) * EMB + h * HDIM;
        #pragma unroll
        for (int t = 0; t < 8; t++) {
            const int d = t * 8 + c0;
            uint32_t hA, lA, hB, lB;
            split_pair_f16(pacc[t][0] * invA, pacc[t][1] * invA, hA, lA);
            split_pair_f16(pacc[t][2] * invB, pacc[t][3] * invB, hB, lB);
            *reinterpret_cast<uint32_t*>(OH + oA + d) = hA;
            *reinterpret_cast<uint32_t*>(OL + oA + d) = lA;
            *reinterpret_cast<uint32_t*>(OH + oB + d) = hB;
            *reinterpret_cast<uint32_t*>(OL + oB + d) = lB;
        }
    }
}

// ---------------------------------------------------------------------------
extern "C" void kernel_launch(void* const* d_in, const int* in_sizes, int n_in,
                              void* d_out, int out_size) {
    const float* hs     = (const float*)d_in[0];
    const float* W_attn = (const float*)d_in[1];
    const float* b_attn = (const float*)d_in[2];
    const float* W_proj = (const float*)d_in[3];
    const float* b_proj = (const float*)d_in[4];
    float* out = (float*)d_out;

    __nv_bfloat16 *QKVH, *QKVL, *AH, *AL, *WH;
    cudaGetSymbolAddress((void**)&QKVH, g_QKVH);
    cudaGetSymbolAddress((void**)&QKVL, g_QKVL);
    cudaGetSymbolAddress((void**)&AH, g_AH);
    cudaGetSymbolAddress((void**)&AL, g_AL);
    cudaGetSymbolAddress((void**)&WH, g_WH);

    static bool attr_set = false;
    if (!attr_set) {
        cudaFuncSetAttribute(gemm_f16x2,
                             cudaFuncAttributeMaxDynamicSharedMemorySize,
                             F16_SMEM_BYTES);
        cudaFuncSetAttribute(attn_tc,
                             cudaFuncAttributeMaxDynamicSharedMemorySize,
                             AT_SMEM_BYTES);
        attr_set = true;
    }

    const int M = BATCH * SEQ;  // 4096
    const int K = EMB;          // 1024

    // 1) hs -> fp16 hi/lo planes; W_attn -> transposed fp16 hi plane
    conv_split_f16<<<(M * K / 4 + 255) / 256, 256>>>(
        hs, (__half*)AH, (__half*)AL, M * K / 4);
    {
        dim3 g(3 * EMB / 32, EMB / 32), t(32, 8);
        conv_T_f16h<<<g, t>>>(W_attn, (__half*)WH, K, 3 * EMB);
    }
    // 2) QKV projection: fp16x2 -> bf16 hi/lo planes
    {
        dim3 grid((3 * EMB) / GBN, M / GBM);
        gemm_f16x2<<<grid, 256, F16_SMEM_BYTES>>>(
            (const __half*)AH, (const __half*)AL, (const __half*)WH,
            b_attn, nullptr, QKVH, QKVL, M, 3 * EMB, K);
    }
    // 3) Sparse attention (bf16x3, register-P) -> exact fp16 planes into AH/AL
    {
        dim3 grid(16, NHEAD, BATCH);
        attn_tc<<<grid, 256, AT_SMEM_BYTES>>>(QKVH, QKVL,
                                              (__half*)AH, (__half*)AL);
    }
    // 4) W_proj -> fp16 hi; output projection fp16x2 (fp32 out)
    {
        dim3 g(EMB / 32, EMB / 32), t(32, 8);
        conv_T_f16h<<<g, t>>>(W_proj, (__half*)WH, K, EMB);
    }
    {
        dim3 grid(EMB / GBN, M / GBM);
        gemm_f16x2<<<grid, 256, F16_SMEM_BYTES>>>(
            (const __half*)AH, (const __half*)AL, (const __half*)WH,
            b_proj, out, nullptr, nullptr, M, EMB, K);
    }
}

// round 15
// speedup vs baseline: 1.0424x; 1.0424x over previous
#include <cuda_runtime.h>
#include <cuda_bf16.h>
#include <cuda_fp16.h>
#include <math.h>
#include <stdint.h>

// Problem constants
#define BATCH 2
#define SEQ   2048
#define EMB   1024
#define NHEAD 16
#define HDIM  64
#define STRIDE_BLK 128
#define CKEEP 8

// Scratch (device globals; no runtime allocation allowed).
__device__ __nv_bfloat16 g_QKVH[(size_t)BATCH * SEQ * 3 * EMB];  // qkv hi plane (bf16)
__device__ __nv_bfloat16 g_QKVL[(size_t)BATCH * SEQ * 3 * EMB];  // qkv lo plane (bf16)
__device__ __nv_bfloat16 g_AH[(size_t)4096 * 1024];
__device__ __nv_bfloat16 g_AL[(size_t)4096 * 1024];
__device__ __nv_bfloat16 g_WH[(size_t)3072 * 1024];              // W_attn^T hi [N][K]
__device__ __nv_bfloat16 g_WP[(size_t)1024 * 1024];              // W_proj^T hi [N][K]

// ---------------------------------------------------------------------------
// helpers
// ---------------------------------------------------------------------------
__device__ __forceinline__ uint32_t bf2_pack(__nv_bfloat16 a, __nv_bfloat16 b) {
    __nv_bfloat162 v(a, b);
    return *reinterpret_cast<uint32_t*>(&v);
}
__device__ __forceinline__ void split_pair(float x, float y, uint32_t& hi, uint32_t& lo) {
    __nv_bfloat16 hx = __float2bfloat16(x), hy = __float2bfloat16(y);
    __nv_bfloat16 lx = __float2bfloat16(x - __bfloat162float(hx));
    __nv_bfloat16 ly = __float2bfloat16(y - __bfloat162float(hy));
    hi = bf2_pack(hx, hy);
    lo = bf2_pack(lx, ly);
}
__device__ __forceinline__ uint32_t h2_pack(__half a, __half b) {
    __half2 v = __halves2half2(a, b);
    return *reinterpret_cast<uint32_t*>(&v);
}
__device__ __forceinline__ void split_pair_f16(float x, float y, uint32_t& hi, uint32_t& lo) {
    __half hx = __float2half_rn(x), hy = __float2half_rn(y);
    __half lx = __float2half_rn(x - __half2float(hx));
    __half ly = __float2half_rn(y - __half2float(hy));
    hi = h2_pack(hx, hy);
    lo = h2_pack(lx, ly);
}
__device__ __forceinline__ void ldsm4(uint32_t& r0, uint32_t& r1,
                                      uint32_t& r2, uint32_t& r3, uint32_t addr) {
    asm volatile("ldmatrix.sync.aligned.m8n8.x4.shared.b16 {%0,%1,%2,%3},[%4];"
                 : "=r"(r0), "=r"(r1), "=r"(r2), "=r"(r3) : "r"(addr));
}
__device__ __forceinline__ void mma_bf16(float* d, const uint32_t* a,
                                         const uint32_t* b) {
    asm volatile(
        "mma.sync.aligned.m16n8k16.row.col.f32.bf16.bf16.f32 "
        "{%0,%1,%2,%3},{%4,%5,%6,%7},{%8,%9},{%0,%1,%2,%3};"
        : "+f"(d[0]), "+f"(d[1]), "+f"(d[2]), "+f"(d[3])
        : "r"(a[0]), "r"(a[1]), "r"(a[2]), "r"(a[3]), "r"(b[0]), "r"(b[1]));
}
__device__ __forceinline__ void mma_f16(float* d, const uint32_t* a,
                                        const uint32_t* b) {
    asm volatile(
        "mma.sync.aligned.m16n8k16.row.col.f32.f16.f16.f32 "
        "{%0,%1,%2,%3},{%4,%5,%6,%7},{%8,%9},{%0,%1,%2,%3};"
        : "+f"(d[0]), "+f"(d[1]), "+f"(d[2]), "+f"(d[3])
        : "r"(a[0]), "r"(a[1]), "r"(a[2]), "r"(a[3]), "r"(b[0]), "r"(b[1]));
}
__device__ __forceinline__ uint32_t smem_u32(const void* p) {
    uint32_t a;
    asm("{.reg .u64 t; cvta.to.shared.u64 t, %1; cvt.u32.u64 %0, t;}" : "=r"(a) : "l"(p));
    return a;
}
__device__ __forceinline__ uint32_t prmt(uint32_t a, uint32_t b, uint32_t s) {
    uint32_t d;
    asm("prmt.b32 %0,%1,%2,%3;" : "=r"(d) : "r"(a), "r"(b), "r"(s));
    return d;
}

// ---------------------------------------------------------------------------
// fp32 -> fp16 hi/lo split, elementwise
// ---------------------------------------------------------------------------
__global__ __launch_bounds__(256) void conv_split_f16(
    const float* __restrict__ X, __half* __restrict__ Hi,
    __half* __restrict__ Lo, int n4)
{
    int i = blockIdx.x * blockDim.x + threadIdx.x;
    if (i >= n4) return;
    float4 v = reinterpret_cast<const float4*>(X)[i];
    uint32_t h0, l0, h1, l1;
    split_pair_f16(v.x, v.y, h0, l0);
    split_pair_f16(v.z, v.w, h1, l1);
    uint2 hh = {h0, h1}, ll = {l0, l1};
    reinterpret_cast<uint2*>(Hi)[i] = hh;
    reinterpret_cast<uint2*>(Lo)[i] = ll;
}

// ---------------------------------------------------------------------------
// Both weight transposes in ONE launch: fp32 [K][N] -> fp16 hi [N][K].
// blockIdx.z = 0 -> (W_attn, N=3072), 1 -> (W_proj, N=1024).
// ---------------------------------------------------------------------------
__global__ __launch_bounds__(256) void conv_T_f16h_dual(
    const float* __restrict__ W0, __half* __restrict__ H0, int N0,
    const float* __restrict__ W1, __half* __restrict__ H1, int N1, int K)
{
    const int which = blockIdx.z;
    const float* W = which ? W1 : W0;
    __half* HiT    = which ? H1 : H0;
    const int N    = which ? N1 : N0;
    const int n0 = blockIdx.x * 32, k0 = blockIdx.y * 32;
    if (n0 >= N) return;
    __shared__ float t[32][33];
    const int tx = threadIdx.x, ty = threadIdx.y;  // 32 x 8
    #pragma unroll
    for (int i = 0; i < 32; i += 8)
        t[ty + i][tx] = W[(size_t)(k0 + ty + i) * N + n0 + tx];
    __syncthreads();
    #pragma unroll
    for (int i = 0; i < 32; i += 8)
        HiT[(size_t)(n0 + ty + i) * K + k0 + tx] = __float2half_rn(t[tx][ty + i]);
}

// ---------------------------------------------------------------------------
// Shared tile geometry
// ---------------------------------------------------------------------------
#define GBM 128
#define GBN 128
#define GBK 32
#define ASTR 40
#define A_CH (GBM * ASTR)
#define B_CH (GBN * ASTR)

// ---------------------------------------------------------------------------
// fp16x2 GEMM (register-prefetch double buffering — proven fastest):
// C = A @ Wt^T + bias, A = Ah+Al fp16 (exact), W = Wh fp16.
// Output fp32 (Cf32) or bf16 hi/lo planes (OH/OL).
// ---------------------------------------------------------------------------
#define F16_SMEM_BYTES ((4 * A_CH + 2 * B_CH) * 2)

__global__ __launch_bounds__(256) void gemm_f16x2(
    const __half* __restrict__ Ah, const __half* __restrict__ Al,
    const __half* __restrict__ Bh,
    const float* __restrict__ bias, float* __restrict__ Cf32,
    __nv_bfloat16* __restrict__ OH, __nv_bfloat16* __restrict__ OL,
    int M, int N, int K)
{
    extern __shared__ __half smh[];
    uint32_t sbase = smem_u32(smh);

    const int tid  = threadIdx.x;
    const int lane = tid & 31;
    const int wid  = tid >> 5;
    const int wm   = wid >> 2;
    const int wn   = wid & 3;
    const int brow = blockIdx.y;
    const int bcol = blockIdx.x;

    const int lr = tid >> 2;
    const int lc = (tid & 3) * 8;

    const __half* Ah0 = Ah + (size_t)(brow * GBM + lr) * K + lc;
    const __half* Al0 = Al + (size_t)(brow * GBM + lr) * K + lc;
    const __half* Bh0 = Bh + (size_t)(bcol * GBN + lr) * K + lc;
    const size_t rstep = (size_t)64 * K;

    auto aoff = [](int buf, int part) { return (buf * 2 + part) * A_CH; };
    auto boff = [](int buf) { return 4 * A_CH + buf * B_CH; };

    float acc[4][4][4] = {};

    {
        const int so = lr * ASTR + lc;
        *reinterpret_cast<uint4*>(smh + aoff(0,0) + so) = *reinterpret_cast<const uint4*>(Ah0);
        *reinterpret_cast<uint4*>(smh + aoff(0,0) + so + 64*ASTR) = *reinterpret_cast<const uint4*>(Ah0 + rstep);
        *reinterpret_cast<uint4*>(smh + aoff(0,1) + so) = *reinterpret_cast<const uint4*>(Al0);
        *reinterpret_cast<uint4*>(smh + aoff(0,1) + so + 64*ASTR) = *reinterpret_cast<const uint4*>(Al0 + rstep);
        *reinterpret_cast<uint4*>(smh + boff(0) + so) = *reinterpret_cast<const uint4*>(Bh0);
        *reinterpret_cast<uint4*>(smh + boff(0) + so + 64*ASTR) = *reinterpret_cast<const uint4*>(Bh0 + rstep);
    }
    __syncthreads();

    const int nK = K / GBK;
    const int mat = lane >> 3;
    const int r8  = lane & 7;

    int buf = 0;
    for (int kt = 0; kt < nK; kt++) {
        uint4 pf[6];
        const bool more = (kt + 1) < nK;
        if (more) {
            const int ko = (kt + 1) * GBK;
            pf[0] = *reinterpret_cast<const uint4*>(Ah0 + ko);
            pf[1] = *reinterpret_cast<const uint4*>(Ah0 + ko + rstep);
            pf[2] = *reinterpret_cast<const uint4*>(Al0 + ko);
            pf[3] = *reinterpret_cast<const uint4*>(Al0 + ko + rstep);
            pf[4] = *reinterpret_cast<const uint4*>(Bh0 + ko);
            pf[5] = *reinterpret_cast<const uint4*>(Bh0 + ko + rstep);
        }

        #pragma unroll
        for (int ks = 0; ks < 2; ks++) {
            uint32_t ah[4][4], al[4][4], bh[4][2];
            #pragma unroll
            for (int mi = 0; mi < 4; mi++) {
                const int row = wm * 64 + mi * 16 + (mat & 1) * 8 + r8;
                const int col = ks * 16 + (mat >> 1) * 8;
                const uint32_t a_addr = sbase + (uint32_t)(aoff(buf,0) + row * ASTR + col) * 2;
                ldsm4(ah[mi][0], ah[mi][1], ah[mi][2], ah[mi][3], a_addr);
                ldsm4(al[mi][0], al[mi][1], al[mi][2], al[mi][3], a_addr + A_CH * 2);
            }
            #pragma unroll
            for (int nt = 0; nt < 2; nt++) {
                const int row = wn * 32 + nt * 16 + (mat >> 1) * 8 + r8;
                const int col = ks * 16 + (mat & 1) * 8;
                const uint32_t b_addr = sbase + (uint32_t)(boff(buf) + row * ASTR + col) * 2;
                uint32_t r0, r1, r2, r3;
                ldsm4(r0, r1, r2, r3, b_addr);
                bh[2*nt][0] = r0; bh[2*nt][1] = r1; bh[2*nt+1][0] = r2; bh[2*nt+1][1] = r3;
            }
            // interleave hi/lo chains across nj for ILP
            #pragma unroll
            for (int mi = 0; mi < 4; mi++) {
                #pragma unroll
                for (int nj = 0; nj < 4; nj++)
                    mma_f16(acc[mi][nj], ah[mi], bh[nj]);
                #pragma unroll
                for (int nj = 0; nj < 4; nj++)
                    mma_f16(acc[mi][nj], al[mi], bh[nj]);
            }
        }

        if (more) {
            const int nb = buf ^ 1;
            const int so = lr * ASTR + lc;
            *reinterpret_cast<uint4*>(smh + aoff(nb,0) + so)           = pf[0];
            *reinterpret_cast<uint4*>(smh + aoff(nb,0) + so + 64*ASTR) = pf[1];
            *reinterpret_cast<uint4*>(smh + aoff(nb,1) + so)           = pf[2];
            *reinterpret_cast<uint4*>(smh + aoff(nb,1) + so + 64*ASTR) = pf[3];
            *reinterpret_cast<uint4*>(smh + boff(nb) + so)             = pf[4];
            *reinterpret_cast<uint4*>(smh + boff(nb) + so + 64*ASTR)   = pf[5];
            __syncthreads();
        }
        buf ^= 1;
    }

    #pragma unroll
    for (int nj = 0; nj < 4; nj++) {
        const int c = bcol * GBN + wn * 32 + nj * 8 + (lane & 3) * 2;
        const float2 bv = *reinterpret_cast<const float2*>(bias + c);
        #pragma unroll
        for (int mi = 0; mi < 4; mi++) {
            const int r0 = brow * GBM + wm * 64 + mi * 16 + (lane >> 2);
            float2 o0, o1;
            o0.x = acc[mi][nj][0] + bv.x;  o0.y = acc[mi][nj][1] + bv.y;
            o1.x = acc[mi][nj][2] + bv.x;  o1.y = acc[mi][nj][3] + bv.y;
            if (Cf32) {
                *reinterpret_cast<float2*>(Cf32 + (size_t)r0 * N + c)       = o0;
                *reinterpret_cast<float2*>(Cf32 + (size_t)(r0 + 8) * N + c) = o1;
            } else {
                uint32_t h0, l0, h1, l1;
                split_pair(o0.x, o0.y, h0, l0);
                split_pair(o1.x, o1.y, h1, l1);
                const size_t e0 = (size_t)r0 * N + c;
                const size_t e1 = (size_t)(r0 + 8) * N + c;
                *reinterpret_cast<uint32_t*>(OH + e0) = h0;
                *reinterpret_cast<uint32_t*>(OL + e0) = l0;
                *reinterpret_cast<uint32_t*>(OH + e1) = h1;
                *reinterpret_cast<uint32_t*>(OL + e1) = l1;
            }
        }
    }
}

// ---------------------------------------------------------------------------
// Tensor-core sparse-causal attention, register-resident P, interleaved mmas.
// ---------------------------------------------------------------------------
#define AT_VSTR 264
#define AT_QSTR 72
#define AT_KSTR 72
#define AT_VTH  0
#define AT_VTL  16896
#define AT_QH   33792
#define AT_QL   43008
#define AT_KH   52224
#define AT_KL   70656
#define AT_SMEM_BYTES (89088 * 2 + 256)

__device__ __forceinline__ int key_map(int j, int nstr, int qb) {
    return (j < nstr) ? ((j >> 3) << 7) + (STRIDE_BLK - CKEEP) + (j & 7)
                      : (qb << 7) + (j - nstr);
}

__global__ __launch_bounds__(256, 1) void attn_tc(
    const __nv_bfloat16* __restrict__ QKVH, const __nv_bfloat16* __restrict__ QKVL,
    __half* __restrict__ OH, __half* __restrict__ OL)
{
    const int qb  = 15 - blockIdx.x;
    const int h   = blockIdx.y;
    const int b   = blockIdx.z;
    const int tid = threadIdx.x;
    const int lane = tid & 31;
    const int wid  = tid >> 5;
    const int nstr = qb * CKEEP;
    const int cnt  = nstr + 128;
    const int gmax = (cnt + 15) >> 4;
    const int q0   = qb * 128;

    extern __shared__ __nv_bfloat16 sb16[];
    const uint32_t sbase = smem_u32(sb16);

    const size_t base = (size_t)b * SEQ * (3 * EMB);

    // --- stage Q ---
    {
        const int row = tid >> 1;
        const int d0  = (tid & 1) * 32;
        const size_t g = base + (size_t)(q0 + row) * (3 * EMB) + h * HDIM + d0;
        const int eo = row * AT_QSTR + d0;
        #pragma unroll
        for (int i = 0; i < 4; i++) {
            *reinterpret_cast<uint4*>(sb16 + AT_QH + eo + i * 8) =
                *reinterpret_cast<const uint4*>(QKVH + g + i * 8);
            *reinterpret_cast<uint4*>(sb16 + AT_QL + eo + i * 8) =
                *reinterpret_cast<const uint4*>(QKVL + g + i * 8);
        }
    }

    // --- stage K (zero-pad only when needed) ---
    {
        const int j = tid;
        if (j < cnt) {
            const int key = key_map(j, nstr, qb);
            const size_t g = base + (size_t)key * (3 * EMB) + EMB + h * HDIM;
            const int eo = j * AT_KSTR;
            #pragma unroll
            for (int i = 0; i < 8; i++) {
                *reinterpret_cast<uint4*>(sb16 + AT_KH + eo + i * 8) =
                    *reinterpret_cast<const uint4*>(QKVH + g + i * 8);
                *reinterpret_cast<uint4*>(sb16 + AT_KL + eo + i * 8) =
                    *reinterpret_cast<const uint4*>(QKVL + g + i * 8);
            }
        } else if (j < 16 * gmax) {
            const uint4 z = {0u, 0u, 0u, 0u};
            const int eo = j * AT_KSTR;
            #pragma unroll
            for (int i = 0; i < 8; i++) {
                *reinterpret_cast<uint4*>(sb16 + AT_KH + eo + i * 8) = z;
                *reinterpret_cast<uint4*>(sb16 + AT_KL + eo + i * 8) = z;
            }
        }
    }

    // --- stage V transposed via PRMT ---
    {
        const int p      = tid & 127;
        const bool lo_pl = tid >= 128;
        const int vtoff  = lo_pl ? AT_VTL : AT_VTH;
        const int k0     = 2 * p;
        if (k0 < cnt) {
            const __nv_bfloat16* plane = lo_pl ? QKVL : QKVH;
            const int keyA = key_map(k0, nstr, qb);
            const int keyB = key_map(k0 + 1, nstr, qb);
            const __nv_bfloat16* ra = plane + base + (size_t)keyA * (3 * EMB) + 2 * EMB + h * HDIM;
            const __nv_bfloat16* rb = plane + base + (size_t)keyB * (3 * EMB) + 2 * EMB + h * HDIM;
            #pragma unroll
            for (int i = 0; i < 8; i++) {
                uint4 a = *reinterpret_cast<const uint4*>(ra + i * 8);
                uint4 c = *reinterpret_cast<const uint4*>(rb + i * 8);
                const uint32_t aw[4] = {a.x, a.y, a.z, a.w};
                const uint32_t cw[4] = {c.x, c.y, c.z, c.w};
                #pragma unroll
                for (int e = 0; e < 4; e++) {
                    const int d = i * 8 + e * 2;
                    *reinterpret_cast<uint32_t*>(sb16 + vtoff + d * AT_VSTR + k0) =
                        prmt(aw[e], cw[e], 0x5410u);
                    *reinterpret_cast<uint32_t*>(sb16 + vtoff + (d + 1) * AT_VSTR + k0) =
                        prmt(aw[e], cw[e], 0x7632u);
                }
            }
        } else if (k0 < 16 * gmax) {
            #pragma unroll
            for (int d = 0; d < 64; d++)
                *reinterpret_cast<uint32_t*>(sb16 + vtoff + d * AT_VSTR + k0) = 0u;
        }
    }
    __syncthreads();

    const int mat = lane >> 3;
    const int r8  = lane & 7;

    // --- scores ---
    float sacc[32][4];
    #pragma unroll
    for (int t = 0; t < 32; t++)
        #pragma unroll
        for (int e = 0; e < 4; e++) sacc[t][e] = 0.f;

    {
        const int arow = wid * 16 + (mat & 1) * 8 + r8;
        #pragma unroll
        for (int ks = 0; ks < 4; ks++) {
            uint32_t ah[4], al[4];
            const uint32_t aaddr = sbase + (uint32_t)(AT_QH + arow * AT_QSTR + ks * 16 + (mat >> 1) * 8) * 2;
            ldsm4(ah[0], ah[1], ah[2], ah[3], aaddr);
            ldsm4(al[0], al[1], al[2], al[3], aaddr + (AT_QL - AT_QH) * 2);
            #pragma unroll
            for (int g = 0; g < 16; g++) {
                if (g < gmax) {
                    const int brow = g * 16 + (mat >> 1) * 8 + r8;
                    const uint32_t baddr = sbase + (uint32_t)(AT_KH + brow * AT_KSTR + ks * 16 + (mat & 1) * 8) * 2;
                    uint32_t bh[2][2], bl[2][2];
                    uint32_t r0, r1, r2, r3;
                    ldsm4(r0, r1, r2, r3, baddr);
                    bh[0][0] = r0; bh[0][1] = r1; bh[1][0] = r2; bh[1][1] = r3;
                    ldsm4(r0, r1, r2, r3, baddr + (AT_KL - AT_KH) * 2);
                    bl[0][0] = r0; bl[0][1] = r1; bl[1][0] = r2; bl[1][1] = r3;
                    // interleaved: two independent accumulator chains in flight
                    mma_bf16(sacc[2 * g],     ah, bh[0]);
                    mma_bf16(sacc[2 * g + 1], ah, bh[1]);
                    mma_bf16(sacc[2 * g],     ah, bl[0]);
                    mma_bf16(sacc[2 * g + 1], ah, bl[1]);
                    mma_bf16(sacc[2 * g],     al, bh[0]);
                    mma_bf16(sacc[2 * g + 1], al, bh[1]);
                }
            }
        }
    }

    // --- in-register masked softmax ---
    const int r0   = lane >> 2;
    const int c0   = (lane & 3) * 2;
    const int rowA = wid * 16 + r0;
    const int rowB = rowA + 8;
    const int limA = nstr + rowA;
    const int limB = nstr + rowB;
    const float scale = 0.125f;

    float mA = -1e30f, mB = -1e30f;
    #pragma unroll
    for (int t = 0; t < 32; t++) {
        if (t < 2 * gmax) {
            const int c = t * 8 + c0;
            sacc[t][0] = (c     <= limA) ? sacc[t][0] * scale : -1e30f;
            sacc[t][1] = (c + 1 <= limA) ? sacc[t][1] * scale : -1e30f;
            sacc[t][2] = (c     <= limB) ? sacc[t][2] * scale : -1e30f;
            sacc[t][3] = (c + 1 <= limB) ? sacc[t][3] * scale : -1e30f;
            mA = fmaxf(mA, fmaxf(sacc[t][0], sacc[t][1]));
            mB = fmaxf(mB, fmaxf(sacc[t][2], sacc[t][3]));
        }
    }
    mA = fmaxf(mA, __shfl_xor_sync(0xffffffffu, mA, 1));
    mA = fmaxf(mA, __shfl_xor_sync(0xffffffffu, mA, 2));
    mB = fmaxf(mB, __shfl_xor_sync(0xffffffffu, mB, 1));
    mB = fmaxf(mB, __shfl_xor_sync(0xffffffffu, mB, 2));

    float sA = 0.f, sB = 0.f;
    #pragma unroll
    for (int t = 0; t < 32; t++) {
        if (t < 2 * gmax) {
            sacc[t][0] = __expf(sacc[t][0] - mA);
            sacc[t][1] = __expf(sacc[t][1] - mA);
            sacc[t][2] = __expf(sacc[t][2] - mB);
            sacc[t][3] = __expf(sacc[t][3] - mB);
            sA += sacc[t][0] + sacc[t][1];
            sB += sacc[t][2] + sacc[t][3];
        }
    }
    sA += __shfl_xor_sync(0xffffffffu, sA, 1);
    sA += __shfl_xor_sync(0xffffffffu, sA, 2);
    sB += __shfl_xor_sync(0xffffffffu, sB, 1);
    sB += __shfl_xor_sync(0xffffffffu, sB, 2);

    // --- O = P @ V, register-resident P ---
    float pacc[8][4];
    #pragma unroll
    for (int t = 0; t < 8; t++)
        #pragma unroll
        for (int e = 0; e < 4; e++) pacc[t][e] = 0.f;

    #pragma unroll
    for (int ks = 0; ks < 16; ks++) {
        if (ks < gmax) {
            uint32_t ah[4], al[4];
            split_pair(sacc[2*ks][0],   sacc[2*ks][1],   ah[0], al[0]);
            split_pair(sacc[2*ks][2],   sacc[2*ks][3],   ah[1], al[1]);
            split_pair(sacc[2*ks+1][0], sacc[2*ks+1][1], ah[2], al[2]);
            split_pair(sacc[2*ks+1][2], sacc[2*ks+1][3], ah[3], al[3]);
            #pragma unroll
            for (int g = 0; g < 4; g++) {
                const int vrow = g * 16 + (mat >> 1) * 8 + r8;
                const uint32_t baddr = sbase + (uint32_t)(AT_VTH + vrow * AT_VSTR + ks * 16 + (mat & 1) * 8) * 2;
                uint32_t bh[2][2], bl[2][2];
                uint32_t r0_, r1_, r2_, r3_;
                ldsm4(r0_, r1_, r2_, r3_, baddr);
                bh[0][0] = r0_; bh[0][1] = r1_; bh[1][0] = r2_; bh[1][1] = r3_;
                ldsm4(r0_, r1_, r2_, r3_, baddr + (AT_VTL - AT_VTH) * 2);
                bl[0][0] = r0_; bl[0][1] = r1_; bl[1][0] = r2_; bl[1][1] = r3_;
                // interleaved chains
                mma_bf16(pacc[2 * g],     ah, bh[0]);
                mma_bf16(pacc[2 * g + 1], ah, bh[1]);
                mma_bf16(pacc[2 * g],     ah, bl[0]);
                mma_bf16(pacc[2 * g + 1], ah, bl[1]);
                mma_bf16(pacc[2 * g],     al, bh[0]);
                mma_bf16(pacc[2 * g + 1], al, bh[1]);
            }
        }
    }

    // --- epilogue: normalize, exact fp16 hi/lo split for proj GEMM ---
    {
        const float invA = 1.0f / sA;
        const float invB = 1.0f / sB;
        const size_t oA = (size_t)(b * SEQ + q0 + rowA) * EMB + h * HDIM;
        const size_t oB = (size_t)(b * SEQ + q0 + rowB) * EMB + h * HDIM;
        #pragma unroll
        for (int t = 0; t < 8; t++) {
            const int d = t * 8 + c0;
            uint32_t hA, lA, hB, lB;
            split_pair_f16(pacc[t][0] * invA, pacc[t][1] * invA, hA, lA);
            split_pair_f16(pacc[t][2] * invB, pacc[t][3] * invB, hB, lB);
            *reinterpret_cast<uint32_t*>(OH + oA + d) = hA;
            *reinterpret_cast<uint32_t*>(OL + oA + d) = lA;
            *reinterpret_cast<uint32_t*>(OH + oB + d) = hB;
            *reinterpret_cast<uint32_t*>(OL + oB + d) = lB;
        }
    }
}

// ---------------------------------------------------------------------------
extern "C" void kernel_launch(void* const* d_in, const int* in_sizes, int n_in,
                              void* d_out, int out_size) {
    const float* hs     = (const float*)d_in[0];
    const float* W_attn = (const float*)d_in[1];
    const float* b_attn = (const float*)d_in[2];
    const float* W_proj = (const float*)d_in[3];
    const float* b_proj = (const float*)d_in[4];
    float* out = (float*)d_out;

    __nv_bfloat16 *QKVH, *QKVL, *AH, *AL, *WH, *WP;
    cudaGetSymbolAddress((void**)&QKVH, g_QKVH);
    cudaGetSymbolAddress((void**)&QKVL, g_QKVL);
    cudaGetSymbolAddress((void**)&AH, g_AH);
    cudaGetSymbolAddress((void**)&AL, g_AL);
    cudaGetSymbolAddress((void**)&WH, g_WH);
    cudaGetSymbolAddress((void**)&WP, g_WP);

    static bool attr_set = false;
    if (!attr_set) {
        cudaFuncSetAttribute(gemm_f16x2,
                             cudaFuncAttributeMaxDynamicSharedMemorySize,
                             F16_SMEM_BYTES);
        cudaFuncSetAttribute(attn_tc,
                             cudaFuncAttributeMaxDynamicSharedMemorySize,
                             AT_SMEM_BYTES);
        attr_set = true;
    }

    const int M = BATCH * SEQ;  // 4096
    const int K = EMB;          // 1024

    // 1) hs -> fp16 hi/lo planes; both W transposes in one launch
    conv_split_f16<<<(M * K / 4 + 255) / 256, 256>>>(
        hs, (__half*)AH, (__half*)AL, M * K / 4);
    {
        dim3 g(3 * EMB / 32, EMB / 32, 2), t(32, 8);
        conv_T_f16h_dual<<<g, t>>>(W_attn, (__half*)WH, 3 * EMB,
                                   W_proj, (__half*)WP, EMB, K);
    }
    // 2) QKV projection: fp16x2 -> bf16 hi/lo planes
    {
        dim3 grid((3 * EMB) / GBN, M / GBM);
        gemm_f16x2<<<grid, 256, F16_SMEM_BYTES>>>(
            (const __half*)AH, (const __half*)AL, (const __half*)WH,
            b_attn, nullptr, QKVH, QKVL, M, 3 * EMB, K);
    }
    // 3) Sparse attention (bf16x3, register-P) -> exact fp16 planes into AH/AL
    {
        dim3 grid(16, NHEAD, BATCH);
        attn_tc<<<grid, 256, AT_SMEM_BYTES>>>(QKVH, QKVL,
                                              (__half*)AH, (__half*)AL);
    }
    // 4) Output projection fp16x2 (fp32 out)
    {
        dim3 grid(EMB / GBN, M / GBM);
        gemm_f16x2<<<grid, 256, F16_SMEM_BYTES>>>(
            (const __half*)AH, (const __half*)AL, (const __half*)WP,
            b_proj, out, nullptr, nullptr, M, EMB, K);
    }
}

// round 16
// speedup vs baseline: 1.0499x; 1.0072x over previous
#include <cuda_runtime.h>
#include <cuda_bf16.h>
#include <cuda_fp16.h>
#include <math.h>
#include <stdint.h>

// Problem constants
#define BATCH 2
#define SEQ   2048
#define EMB   1024
#define NHEAD 16
#define HDIM  64
#define STRIDE_BLK 128
#define CKEEP 8

// Scratch (device globals; no runtime allocation allowed).
__device__ __nv_bfloat16 g_QKVH[(size_t)BATCH * SEQ * 3 * EMB];  // qkv hi plane (bf16)
__device__ __nv_bfloat16 g_QKVL[(size_t)BATCH * SEQ * 3 * EMB];  // qkv lo plane (bf16)
__device__ __nv_bfloat16 g_AH[(size_t)4096 * 1024];
__device__ __nv_bfloat16 g_AL[(size_t)4096 * 1024];
__device__ __nv_bfloat16 g_WH[(size_t)3072 * 1024];              // W_attn^T hi [N][K]
__device__ __nv_bfloat16 g_WP[(size_t)1024 * 1024];              // W_proj^T hi [N][K]

// ---------------------------------------------------------------------------
// helpers
// ---------------------------------------------------------------------------
__device__ __forceinline__ uint32_t bf2_pack(__nv_bfloat16 a, __nv_bfloat16 b) {
    __nv_bfloat162 v(a, b);
    return *reinterpret_cast<uint32_t*>(&v);
}
__device__ __forceinline__ void split_pair(float x, float y, uint32_t& hi, uint32_t& lo) {
    __nv_bfloat16 hx = __float2bfloat16(x), hy = __float2bfloat16(y);
    __nv_bfloat16 lx = __float2bfloat16(x - __bfloat162float(hx));
    __nv_bfloat16 ly = __float2bfloat16(y - __bfloat162float(hy));
    hi = bf2_pack(hx, hy);
    lo = bf2_pack(lx, ly);
}
__device__ __forceinline__ uint32_t h2_pack(__half a, __half b) {
    __half2 v = __halves2half2(a, b);
    return *reinterpret_cast<uint32_t*>(&v);
}
__device__ __forceinline__ void split_pair_f16(float x, float y, uint32_t& hi, uint32_t& lo) {
    __half hx = __float2half_rn(x), hy = __float2half_rn(y);
    __half lx = __float2half_rn(x - __half2float(hx));
    __half ly = __float2half_rn(y - __half2float(hy));
    hi = h2_pack(hx, hy);
    lo = h2_pack(lx, ly);
}
__device__ __forceinline__ void ldsm4(uint32_t& r0, uint32_t& r1,
                                      uint32_t& r2, uint32_t& r3, uint32_t addr) {
    asm volatile("ldmatrix.sync.aligned.m8n8.x4.shared.b16 {%0,%1,%2,%3},[%4];"
                 : "=r"(r0), "=r"(r1), "=r"(r2), "=r"(r3) : "r"(addr));
}
__device__ __forceinline__ void ldsm4t(uint32_t& r0, uint32_t& r1,
                                       uint32_t& r2, uint32_t& r3, uint32_t addr) {
    asm volatile("ldmatrix.sync.aligned.m8n8.x4.trans.shared.b16 {%0,%1,%2,%3},[%4];"
                 : "=r"(r0), "=r"(r1), "=r"(r2), "=r"(r3) : "r"(addr));
}
__device__ __forceinline__ void mma_bf16(float* d, const uint32_t* a,
                                         const uint32_t* b) {
    asm volatile(
        "mma.sync.aligned.m16n8k16.row.col.f32.bf16.bf16.f32 "
        "{%0,%1,%2,%3},{%4,%5,%6,%7},{%8,%9},{%0,%1,%2,%3};"
        : "+f"(d[0]), "+f"(d[1]), "+f"(d[2]), "+f"(d[3])
        : "r"(a[0]), "r"(a[1]), "r"(a[2]), "r"(a[3]), "r"(b[0]), "r"(b[1]));
}
__device__ __forceinline__ void mma_f16(float* d, const uint32_t* a,
                                        const uint32_t* b) {
    asm volatile(
        "mma.sync.aligned.m16n8k16.row.col.f32.f16.f16.f32 "
        "{%0,%1,%2,%3},{%4,%5,%6,%7},{%8,%9},{%0,%1,%2,%3};"
        : "+f"(d[0]), "+f"(d[1]), "+f"(d[2]), "+f"(d[3])
        : "r"(a[0]), "r"(a[1]), "r"(a[2]), "r"(a[3]), "r"(b[0]), "r"(b[1]));
}
__device__ __forceinline__ uint32_t smem_u32(const void* p) {
    uint32_t a;
    asm("{.reg .u64 t; cvta.to.shared.u64 t, %1; cvt.u32.u64 %0, t;}" : "=r"(a) : "l"(p));
    return a;
}

// ---------------------------------------------------------------------------
// fp32 -> fp16 hi/lo split, elementwise
// ---------------------------------------------------------------------------
__global__ __launch_bounds__(256) void conv_split_f16(
    const float* __restrict__ X, __half* __restrict__ Hi,
    __half* __restrict__ Lo, int n4)
{
    int i = blockIdx.x * blockDim.x + threadIdx.x;
    if (i >= n4) return;
    float4 v = reinterpret_cast<const float4*>(X)[i];
    uint32_t h0, l0, h1, l1;
    split_pair_f16(v.x, v.y, h0, l0);
    split_pair_f16(v.z, v.w, h1, l1);
    uint2 hh = {h0, h1}, ll = {l0, l1};
    reinterpret_cast<uint2*>(Hi)[i] = hh;
    reinterpret_cast<uint2*>(Lo)[i] = ll;
}

// ---------------------------------------------------------------------------
// Both weight transposes in ONE launch: fp32 [K][N] -> fp16 hi [N][K].
// ---------------------------------------------------------------------------
__global__ __launch_bounds__(256) void conv_T_f16h_dual(
    const float* __restrict__ W0, __half* __restrict__ H0, int N0,
    const float* __restrict__ W1, __half* __restrict__ H1, int N1, int K)
{
    const int which = blockIdx.z;
    const float* W = which ? W1 : W0;
    __half* HiT    = which ? H1 : H0;
    const int N    = which ? N1 : N0;
    const int n0 = blockIdx.x * 32, k0 = blockIdx.y * 32;
    if (n0 >= N) return;
    __shared__ float t[32][33];
    const int tx = threadIdx.x, ty = threadIdx.y;  // 32 x 8
    #pragma unroll
    for (int i = 0; i < 32; i += 8)
        t[ty + i][tx] = W[(size_t)(k0 + ty + i) * N + n0 + tx];
    __syncthreads();
    #pragma unroll
    for (int i = 0; i < 32; i += 8)
        HiT[(size_t)(n0 + ty + i) * K + k0 + tx] = __float2half_rn(t[tx][ty + i]);
}

// ---------------------------------------------------------------------------
// Shared tile geometry
// ---------------------------------------------------------------------------
#define GBM 128
#define GBN 128
#define GBK 32
#define ASTR 40
#define A_CH (GBM * ASTR)
#define B_CH (GBN * ASTR)

// ---------------------------------------------------------------------------
// fp16x2 GEMM (register-prefetch double buffering — proven fastest):
// C = A @ Wt^T + bias, A = Ah+Al fp16 (exact), W = Wh fp16.
// ---------------------------------------------------------------------------
#define F16_SMEM_BYTES ((4 * A_CH + 2 * B_CH) * 2)

__global__ __launch_bounds__(256) void gemm_f16x2(
    const __half* __restrict__ Ah, const __half* __restrict__ Al,
    const __half* __restrict__ Bh,
    const float* __restrict__ bias, float* __restrict__ Cf32,
    __nv_bfloat16* __restrict__ OH, __nv_bfloat16* __restrict__ OL,
    int M, int N, int K)
{
    extern __shared__ __half smh[];
    uint32_t sbase = smem_u32(smh);

    const int tid  = threadIdx.x;
    const int lane = tid & 31;
    const int wid  = tid >> 5;
    const int wm   = wid >> 2;
    const int wn   = wid & 3;
    const int brow = blockIdx.y;
    const int bcol = blockIdx.x;

    const int lr = tid >> 2;
    const int lc = (tid & 3) * 8;

    const __half* Ah0 = Ah + (size_t)(brow * GBM + lr) * K + lc;
    const __half* Al0 = Al + (size_t)(brow * GBM + lr) * K + lc;
    const __half* Bh0 = Bh + (size_t)(bcol * GBN + lr) * K + lc;
    const size_t rstep = (size_t)64 * K;

    auto aoff = [](int buf, int part) { return (buf * 2 + part) * A_CH; };
    auto boff = [](int buf) { return 4 * A_CH + buf * B_CH; };

    float acc[4][4][4] = {};

    {
        const int so = lr * ASTR + lc;
        *reinterpret_cast<uint4*>(smh + aoff(0,0) + so) = *reinterpret_cast<const uint4*>(Ah0);
        *reinterpret_cast<uint4*>(smh + aoff(0,0) + so + 64*ASTR) = *reinterpret_cast<const uint4*>(Ah0 + rstep);
        *reinterpret_cast<uint4*>(smh + aoff(0,1) + so) = *reinterpret_cast<const uint4*>(Al0);
        *reinterpret_cast<uint4*>(smh + aoff(0,1) + so + 64*ASTR) = *reinterpret_cast<const uint4*>(Al0 + rstep);
        *reinterpret_cast<uint4*>(smh + boff(0) + so) = *reinterpret_cast<const uint4*>(Bh0);
        *reinterpret_cast<uint4*>(smh + boff(0) + so + 64*ASTR) = *reinterpret_cast<const uint4*>(Bh0 + rstep);
    }
    __syncthreads();

    const int nK = K / GBK;
    const int mat = lane >> 3;
    const int r8  = lane & 7;

    int buf = 0;
    for (int kt = 0; kt < nK; kt++) {
        uint4 pf[6];
        const bool more = (kt + 1) < nK;
        if (more) {
            const int ko = (kt + 1) * GBK;
            pf[0] = *reinterpret_cast<const uint4*>(Ah0 + ko);
            pf[1] = *reinterpret_cast<const uint4*>(Ah0 + ko + rstep);
            pf[2] = *reinterpret_cast<const uint4*>(Al0 + ko);
            pf[3] = *reinterpret_cast<const uint4*>(Al0 + ko + rstep);
            pf[4] = *reinterpret_cast<const uint4*>(Bh0 + ko);
            pf[5] = *reinterpret_cast<const uint4*>(Bh0 + ko + rstep);
        }

        #pragma unroll
        for (int ks = 0; ks < 2; ks++) {
            uint32_t ah[4][4], al[4][4], bh[4][2];
            #pragma unroll
            for (int mi = 0; mi < 4; mi++) {
                const int row = wm * 64 + mi * 16 + (mat & 1) * 8 + r8;
                const int col = ks * 16 + (mat >> 1) * 8;
                const uint32_t a_addr = sbase + (uint32_t)(aoff(buf,0) + row * ASTR + col) * 2;
                ldsm4(ah[mi][0], ah[mi][1], ah[mi][2], ah[mi][3], a_addr);
                ldsm4(al[mi][0], al[mi][1], al[mi][2], al[mi][3], a_addr + A_CH * 2);
            }
            #pragma unroll
            for (int nt = 0; nt < 2; nt++) {
                const int row = wn * 32 + nt * 16 + (mat >> 1) * 8 + r8;
                const int col = ks * 16 + (mat & 1) * 8;
                const uint32_t b_addr = sbase + (uint32_t)(boff(buf) + row * ASTR + col) * 2;
                uint32_t r0, r1, r2, r3;
                ldsm4(r0, r1, r2, r3, b_addr);
                bh[2*nt][0] = r0; bh[2*nt][1] = r1; bh[2*nt+1][0] = r2; bh[2*nt+1][1] = r3;
            }
            #pragma unroll
            for (int mi = 0; mi < 4; mi++) {
                #pragma unroll
                for (int nj = 0; nj < 4; nj++)
                    mma_f16(acc[mi][nj], ah[mi], bh[nj]);
                #pragma unroll
                for (int nj = 0; nj < 4; nj++)
                    mma_f16(acc[mi][nj], al[mi], bh[nj]);
            }
        }

        if (more) {
            const int nb = buf ^ 1;
            const int so = lr * ASTR + lc;
            *reinterpret_cast<uint4*>(smh + aoff(nb,0) + so)           = pf[0];
            *reinterpret_cast<uint4*>(smh + aoff(nb,0) + so + 64*ASTR) = pf[1];
            *reinterpret_cast<uint4*>(smh + aoff(nb,1) + so)           = pf[2];
            *reinterpret_cast<uint4*>(smh + aoff(nb,1) + so + 64*ASTR) = pf[3];
            *reinterpret_cast<uint4*>(smh + boff(nb) + so)             = pf[4];
            *reinterpret_cast<uint4*>(smh + boff(nb) + so + 64*ASTR)   = pf[5];
            __syncthreads();
        }
        buf ^= 1;
    }

    #pragma unroll
    for (int nj = 0; nj < 4; nj++) {
        const int c = bcol * GBN + wn * 32 + nj * 8 + (lane & 3) * 2;
        const float2 bv = *reinterpret_cast<const float2*>(bias + c);
        #pragma unroll
        for (int mi = 0; mi < 4; mi++) {
            const int r0 = brow * GBM + wm * 64 + mi * 16 + (lane >> 2);
            float2 o0, o1;
            o0.x = acc[mi][nj][0] + bv.x;  o0.y = acc[mi][nj][1] + bv.y;
            o1.x = acc[mi][nj][2] + bv.x;  o1.y = acc[mi][nj][3] + bv.y;
            if (Cf32) {
                *reinterpret_cast<float2*>(Cf32 + (size_t)r0 * N + c)       = o0;
                *reinterpret_cast<float2*>(Cf32 + (size_t)(r0 + 8) * N + c) = o1;
            } else {
                uint32_t h0, l0, h1, l1;
                split_pair(o0.x, o0.y, h0, l0);
                split_pair(o1.x, o1.y, h1, l1);
                const size_t e0 = (size_t)r0 * N + c;
                const size_t e1 = (size_t)(r0 + 8) * N + c;
                *reinterpret_cast<uint32_t*>(OH + e0) = h0;
                *reinterpret_cast<uint32_t*>(OL + e0) = l0;
                *reinterpret_cast<uint32_t*>(OH + e1) = h1;
                *reinterpret_cast<uint32_t*>(OL + e1) = l1;
            }
        }
    }
}

// ---------------------------------------------------------------------------
// Tensor-core sparse-causal attention, register-resident P.
// V staged ROW-major (like K) and transposed at load via ldmatrix.trans —
// removes the 64-scattered-STS + 64-PRMT transpose staging.
// smem (bf16 elem offsets): Qh@0 Ql@9216 Kh@18432 Kl@36864 Vh@55296 Vl@73728
// ---------------------------------------------------------------------------
#define AT_QSTR 72
#define AT_KSTR 72
#define AT_QH   0
#define AT_QL   9216
#define AT_KH   18432
#define AT_KL   36864
#define AT_VH   55296
#define AT_VL   73728
#define AT_SMEM_BYTES (92160 * 2 + 256)

__device__ __forceinline__ int key_map(int j, int nstr, int qb) {
    return (j < nstr) ? ((j >> 3) << 7) + (STRIDE_BLK - CKEEP) + (j & 7)
                      : (qb << 7) + (j - nstr);
}

__global__ __launch_bounds__(256, 1) void attn_tc(
    const __nv_bfloat16* __restrict__ QKVH, const __nv_bfloat16* __restrict__ QKVL,
    __half* __restrict__ OH, __half* __restrict__ OL)
{
    const int qb  = 15 - blockIdx.x;
    const int h   = blockIdx.y;
    const int b   = blockIdx.z;
    const int tid = threadIdx.x;
    const int lane = tid & 31;
    const int wid  = tid >> 5;
    const int nstr = qb * CKEEP;
    const int cnt  = nstr + 128;
    const int gmax = (cnt + 15) >> 4;
    const int q0   = qb * 128;

    extern __shared__ __nv_bfloat16 sb16[];
    const uint32_t sbase = smem_u32(sb16);

    const size_t base = (size_t)b * SEQ * (3 * EMB);

    // --- stage Q ---
    {
        const int row = tid >> 1;
        const int d0  = (tid & 1) * 32;
        const size_t g = base + (size_t)(q0 + row) * (3 * EMB) + h * HDIM + d0;
        const int eo = row * AT_QSTR + d0;
        #pragma unroll
        for (int i = 0; i < 4; i++) {
            *reinterpret_cast<uint4*>(sb16 + AT_QH + eo + i * 8) =
                *reinterpret_cast<const uint4*>(QKVH + g + i * 8);
            *reinterpret_cast<uint4*>(sb16 + AT_QL + eo + i * 8) =
                *reinterpret_cast<const uint4*>(QKVL + g + i * 8);
        }
    }

    // --- stage K and V row-major (thread j = key slot) ---
    {
        const int j = tid;
        if (j < cnt) {
            const int key = key_map(j, nstr, qb);
            const size_t gk = base + (size_t)key * (3 * EMB) + EMB + h * HDIM;
            const size_t gv = gk + EMB;
            const int eo = j * AT_KSTR;
            #pragma unroll
            for (int i = 0; i < 8; i++) {
                *reinterpret_cast<uint4*>(sb16 + AT_KH + eo + i * 8) =
                    *reinterpret_cast<const uint4*>(QKVH + gk + i * 8);
                *reinterpret_cast<uint4*>(sb16 + AT_KL + eo + i * 8) =
                    *reinterpret_cast<const uint4*>(QKVL + gk + i * 8);
                *reinterpret_cast<uint4*>(sb16 + AT_VH + eo + i * 8) =
                    *reinterpret_cast<const uint4*>(QKVH + gv + i * 8);
                *reinterpret_cast<uint4*>(sb16 + AT_VL + eo + i * 8) =
                    *reinterpret_cast<const uint4*>(QKVL + gv + i * 8);
            }
        } else if (j < 16 * gmax) {
            const uint4 z = {0u, 0u, 0u, 0u};
            const int eo = j * AT_KSTR;
            #pragma unroll
            for (int i = 0; i < 8; i++) {
                *reinterpret_cast<uint4*>(sb16 + AT_KH + eo + i * 8) = z;
                *reinterpret_cast<uint4*>(sb16 + AT_KL + eo + i * 8) = z;
                *reinterpret_cast<uint4*>(sb16 + AT_VH + eo + i * 8) = z;
                *reinterpret_cast<uint4*>(sb16 + AT_VL + eo + i * 8) = z;
            }
        }
    }
    __syncthreads();

    const int mat = lane >> 3;
    const int r8  = lane & 7;

    // --- scores ---
    float sacc[32][4];
    #pragma unroll
    for (int t = 0; t < 32; t++)
        #pragma unroll
        for (int e = 0; e < 4; e++) sacc[t][e] = 0.f;

    {
        const int arow = wid * 16 + (mat & 1) * 8 + r8;
        #pragma unroll
        for (int ks = 0; ks < 4; ks++) {
            uint32_t ah[4], al[4];
            const uint32_t aaddr = sbase + (uint32_t)(AT_QH + arow * AT_QSTR + ks * 16 + (mat >> 1) * 8) * 2;
            ldsm4(ah[0], ah[1], ah[2], ah[3], aaddr);
            ldsm4(al[0], al[1], al[2], al[3], aaddr + (AT_QL - AT_QH) * 2);
            #pragma unroll
            for (int g = 0; g < 16; g++) {
                if (g < gmax) {
                    const int brow = g * 16 + (mat >> 1) * 8 + r8;
                    const uint32_t baddr = sbase + (uint32_t)(AT_KH + brow * AT_KSTR + ks * 16 + (mat & 1) * 8) * 2;
                    uint32_t bh[2][2], bl[2][2];
                    uint32_t r0, r1, r2, r3;
                    ldsm4(r0, r1, r2, r3, baddr);
                    bh[0][0] = r0; bh[0][1] = r1; bh[1][0] = r2; bh[1][1] = r3;
                    ldsm4(r0, r1, r2, r3, baddr + (AT_KL - AT_KH) * 2);
                    bl[0][0] = r0; bl[0][1] = r1; bl[1][0] = r2; bl[1][1] = r3;
                    mma_bf16(sacc[2 * g],     ah, bh[0]);
                    mma_bf16(sacc[2 * g + 1], ah, bh[1]);
                    mma_bf16(sacc[2 * g],     ah, bl[0]);
                    mma_bf16(sacc[2 * g + 1], ah, bl[1]);
                    mma_bf16(sacc[2 * g],     al, bh[0]);
                    mma_bf16(sacc[2 * g + 1], al, bh[1]);
                }
            }
        }
    }

    // --- in-register masked softmax ---
    const int r0   = lane >> 2;
    const int c0   = (lane & 3) * 2;
    const int rowA = wid * 16 + r0;
    const int rowB = rowA + 8;
    const int limA = nstr + rowA;
    const int limB = nstr + rowB;
    const float scale = 0.125f;

    float mA = -1e30f, mB = -1e30f;
    #pragma unroll
    for (int t = 0; t < 32; t++) {
        if (t < 2 * gmax) {
            const int c = t * 8 + c0;
            sacc[t][0] = (c     <= limA) ? sacc[t][0] * scale : -1e30f;
            sacc[t][1] = (c + 1 <= limA) ? sacc[t][1] * scale : -1e30f;
            sacc[t][2] = (c     <= limB) ? sacc[t][2] * scale : -1e30f;
            sacc[t][3] = (c + 1 <= limB) ? sacc[t][3] * scale : -1e30f;
            mA = fmaxf(mA, fmaxf(sacc[t][0], sacc[t][1]));
            mB = fmaxf(mB, fmaxf(sacc[t][2], sacc[t][3]));
        }
    }
    mA = fmaxf(mA, __shfl_xor_sync(0xffffffffu, mA, 1));
    mA = fmaxf(mA, __shfl_xor_sync(0xffffffffu, mA, 2));
    mB = fmaxf(mB, __shfl_xor_sync(0xffffffffu, mB, 1));
    mB = fmaxf(mB, __shfl_xor_sync(0xffffffffu, mB, 2));

    float sA = 0.f, sB = 0.f;
    #pragma unroll
    for (int t = 0; t < 32; t++) {
        if (t < 2 * gmax) {
            sacc[t][0] = __expf(sacc[t][0] - mA);
            sacc[t][1] = __expf(sacc[t][1] - mA);
            sacc[t][2] = __expf(sacc[t][2] - mB);
            sacc[t][3] = __expf(sacc[t][3] - mB);
            sA += sacc[t][0] + sacc[t][1];
            sB += sacc[t][2] + sacc[t][3];
        }
    }
    sA += __shfl_xor_sync(0xffffffffu, sA, 1);
    sA += __shfl_xor_sync(0xffffffffu, sA, 2);
    sB += __shfl_xor_sync(0xffffffffu, sB, 1);
    sB += __shfl_xor_sync(0xffffffffu, sB, 2);

    // --- O = P @ V, register-resident P, V transposed at load (ldsm.trans) ---
    float pacc[8][4];
    #pragma unroll
    for (int t = 0; t < 8; t++)
        #pragma unroll
        for (int e = 0; e < 4; e++) pacc[t][e] = 0.f;

    #pragma unroll
    for (int ks = 0; ks < 16; ks++) {
        if (ks < gmax) {
            uint32_t ah[4], al[4];
            split_pair(sacc[2*ks][0],   sacc[2*ks][1],   ah[0], al[0]);
            split_pair(sacc[2*ks][2],   sacc[2*ks][3],   ah[1], al[1]);
            split_pair(sacc[2*ks+1][0], sacc[2*ks+1][1], ah[2], al[2]);
            split_pair(sacc[2*ks+1][2], sacc[2*ks+1][3], ah[3], al[3]);
            // V fragment: rows = keys, trans -> [d][key]; matrix layout:
            //   mat0/1 = k-halves for d-group 0, mat2/3 = for d-group 1
            const int vkrow = ks * 16 + (mat & 1) * 8 + r8;
            #pragma unroll
            for (int g = 0; g < 4; g++) {
                const uint32_t baddr = sbase + (uint32_t)(AT_VH + vkrow * AT_KSTR + g * 16 + (mat >> 1) * 8) * 2;
                uint32_t bh[2][2], bl[2][2];
                uint32_t r0_, r1_, r2_, r3_;
                ldsm4t(r0_, r1_, r2_, r3_, baddr);
                bh[0][0] = r0_; bh[0][1] = r1_; bh[1][0] = r2_; bh[1][1] = r3_;
                ldsm4t(r0_, r1_, r2_, r3_, baddr + (AT_VL - AT_VH) * 2);
                bl[0][0] = r0_; bl[0][1] = r1_; bl[1][0] = r2_; bl[1][1] = r3_;
                mma_bf16(pacc[2 * g],     ah, bh[0]);
                mma_bf16(pacc[2 * g + 1], ah, bh[1]);
                mma_bf16(pacc[2 * g],     ah, bl[0]);
                mma_bf16(pacc[2 * g + 1], ah, bl[1]);
                mma_bf16(pacc[2 * g],     al, bh[0]);
                mma_bf16(pacc[2 * g + 1], al, bh[1]);
            }
        }
    }

    // --- epilogue: normalize, exact fp16 hi/lo split for proj GEMM ---
    {
        const float invA = 1.0f / sA;
        const float invB = 1.0f / sB;
        const size_t oA = (size_t)(b * SEQ + q0 + rowA) * EMB + h * HDIM;
        const size_t oB = (size_t)(b * SEQ + q0 + rowB) * EMB + h * HDIM;
        #pragma unroll
        for (int t = 0; t < 8; t++) {
            const int d = t * 8 + c0;
            uint32_t hA, lA, hB, lB;
            split_pair_f16(pacc[t][0] * invA, pacc[t][1] * invA, hA, lA);
            split_pair_f16(pacc[t][2] * invB, pacc[t][3] * invB, hB, lB);
            *reinterpret_cast<uint32_t*>(OH + oA + d) = hA;
            *reinterpret_cast<uint32_t*>(OL + oA + d) = lA;
            *reinterpret_cast<uint32_t*>(OH + oB + d) = hB;
            *reinterpret_cast<uint32_t*>(OL + oB + d) = lB;
        }
    }
}

// ---------------------------------------------------------------------------
extern "C" void kernel_launch(void* const* d_in, const int* in_sizes, int n_in,
                              void* d_out, int out_size) {
    const float* hs     = (const float*)d_in[0];
    const float* W_attn = (const float*)d_in[1];
    const float* b_attn = (const float*)d_in[2];
    const float* W_proj = (const float*)d_in[3];
    const float* b_proj = (const float*)d_in[4];
    float* out = (float*)d_out;

    __nv_bfloat16 *QKVH, *QKVL, *AH, *AL, *WH, *WP;
    cudaGetSymbolAddress((void**)&QKVH, g_QKVH);
    cudaGetSymbolAddress((void**)&QKVL, g_QKVL);
    cudaGetSymbolAddress((void**)&AH, g_AH);
    cudaGetSymbolAddress((void**)&AL, g_AL);
    cudaGetSymbolAddress((void**)&WH, g_WH);
    cudaGetSymbolAddress((void**)&WP, g_WP);

    static bool attr_set = false;
    if (!attr_set) {
        cudaFuncSetAttribute(gemm_f16x2,
                             cudaFuncAttributeMaxDynamicSharedMemorySize,
                             F16_SMEM_BYTES);
        cudaFuncSetAttribute(attn_tc,
                             cudaFuncAttributeMaxDynamicSharedMemorySize,
                             AT_SMEM_BYTES);
        attr_set = true;
    }

    const int M = BATCH * SEQ;  // 4096
    const int K = EMB;          // 1024

    // 1) hs -> fp16 hi/lo planes; both W transposes in one launch
    conv_split_f16<<<(M * K / 4 + 255) / 256, 256>>>(
        hs, (__half*)AH, (__half*)AL, M * K / 4);
    {
        dim3 g(3 * EMB / 32, EMB / 32, 2), t(32, 8);
        conv_T_f16h_dual<<<g, t>>>(W_attn, (__half*)WH, 3 * EMB,
                                   W_proj, (__half*)WP, EMB, K);
    }
    // 2) QKV projection: fp16x2 -> bf16 hi/lo planes
    {
        dim3 grid((3 * EMB) / GBN, M / GBM);
        gemm_f16x2<<<grid, 256, F16_SMEM_BYTES>>>(
            (const __half*)AH, (const __half*)AL, (const __half*)WH,
            b_attn, nullptr, QKVH, QKVL, M, 3 * EMB, K);
    }
    // 3) Sparse attention -> exact fp16 planes into AH/AL
    {
        dim3 grid(16, NHEAD, BATCH);
        attn_tc<<<grid, 256, AT_SMEM_BYTES>>>(QKVH, QKVL,
                                              (__half*)AH, (__half*)AL);
    }
    // 4) Output projection fp16x2 (fp32 out)
    {
        dim3 grid(EMB / GBN, M / GBM);
        gemm_f16x2<<<grid, 256, F16_SMEM_BYTES>>>(
            (const __half*)AH, (const __half*)AL, (const __half*)WP,
            b_proj, out, nullptr, nullptr, M, EMB, K);
    }
}

// round 17
// speedup vs baseline: 1.1065x; 1.0539x over previous
#include <cuda_runtime.h>
#include <cuda_bf16.h>
#include <cuda_fp16.h>
#include <math.h>
#include <stdint.h>

// Problem constants
#define BATCH 2
#define SEQ   2048
#define EMB   1024
#define NHEAD 16
#define HDIM  64
#define STRIDE_BLK 128
#define CKEEP 8

// Scratch (device globals; no runtime allocation allowed).
__device__ __half g_QKVH[(size_t)BATCH * SEQ * 3 * EMB];  // qkv hi plane (fp16)
__device__ __half g_QKVL[(size_t)BATCH * SEQ * 3 * EMB];  // qkv lo plane (fp16)
__device__ __half g_AH[(size_t)4096 * 1024];
__device__ __half g_AL[(size_t)4096 * 1024];
__device__ __half g_WH[(size_t)3072 * 1024];              // W_attn^T hi [N][K]
__device__ __half g_WP[(size_t)1024 * 1024];              // W_proj^T hi [N][K]

// ---------------------------------------------------------------------------
// helpers
// ---------------------------------------------------------------------------
__device__ __forceinline__ uint32_t h2_pack(__half a, __half b) {
    __half2 v = __halves2half2(a, b);
    return *reinterpret_cast<uint32_t*>(&v);
}
__device__ __forceinline__ void split_pair_f16(float x, float y, uint32_t& hi, uint32_t& lo) {
    __half hx = __float2half_rn(x), hy = __float2half_rn(y);
    __half lx = __float2half_rn(x - __half2float(hx));
    __half ly = __float2half_rn(y - __half2float(hy));
    hi = h2_pack(hx, hy);
    lo = h2_pack(lx, ly);
}
__device__ __forceinline__ void ldsm4(uint32_t& r0, uint32_t& r1,
                                      uint32_t& r2, uint32_t& r3, uint32_t addr) {
    asm volatile("ldmatrix.sync.aligned.m8n8.x4.shared.b16 {%0,%1,%2,%3},[%4];"
                 : "=r"(r0), "=r"(r1), "=r"(r2), "=r"(r3) : "r"(addr));
}
__device__ __forceinline__ void ldsm4t(uint32_t& r0, uint32_t& r1,
                                       uint32_t& r2, uint32_t& r3, uint32_t addr) {
    asm volatile("ldmatrix.sync.aligned.m8n8.x4.trans.shared.b16 {%0,%1,%2,%3},[%4];"
                 : "=r"(r0), "=r"(r1), "=r"(r2), "=r"(r3) : "r"(addr));
}
__device__ __forceinline__ void mma_f16(float* d, const uint32_t* a,
                                        const uint32_t* b) {
    asm volatile(
        "mma.sync.aligned.m16n8k16.row.col.f32.f16.f16.f32 "
        "{%0,%1,%2,%3},{%4,%5,%6,%7},{%8,%9},{%0,%1,%2,%3};"
        : "+f"(d[0]), "+f"(d[1]), "+f"(d[2]), "+f"(d[3])
        : "r"(a[0]), "r"(a[1]), "r"(a[2]), "r"(a[3]), "r"(b[0]), "r"(b[1]));
}
__device__ __forceinline__ uint32_t smem_u32(const void* p) {
    uint32_t a;
    asm("{.reg .u64 t; cvta.to.shared.u64 t, %1; cvt.u32.u64 %0, t;}" : "=r"(a) : "l"(p));
    return a;
}

// ---------------------------------------------------------------------------
// fp32 -> fp16 hi/lo split, elementwise
// ---------------------------------------------------------------------------
__global__ __launch_bounds__(256) void conv_split_f16(
    const float* __restrict__ X, __half* __restrict__ Hi,
    __half* __restrict__ Lo, int n4)
{
    int i = blockIdx.x * blockDim.x + threadIdx.x;
    if (i >= n4) return;
    float4 v = reinterpret_cast<const float4*>(X)[i];
    uint32_t h0, l0, h1, l1;
    split_pair_f16(v.x, v.y, h0, l0);
    split_pair_f16(v.z, v.w, h1, l1);
    uint2 hh = {h0, h1}, ll = {l0, l1};
    reinterpret_cast<uint2*>(Hi)[i] = hh;
    reinterpret_cast<uint2*>(Lo)[i] = ll;
}

// ---------------------------------------------------------------------------
// Both weight transposes in ONE launch: fp32 [K][N] -> fp16 hi [N][K].
// ---------------------------------------------------------------------------
__global__ __launch_bounds__(256) void conv_T_f16h_dual(
    const float* __restrict__ W0, __half* __restrict__ H0, int N0,
    const float* __restrict__ W1, __half* __restrict__ H1, int N1, int K)
{
    const int which = blockIdx.z;
    const float* W = which ? W1 : W0;
    __half* HiT    = which ? H1 : H0;
    const int N    = which ? N1 : N0;
    const int n0 = blockIdx.x * 32, k0 = blockIdx.y * 32;
    if (n0 >= N) return;
    __shared__ float t[32][33];
    const int tx = threadIdx.x, ty = threadIdx.y;  // 32 x 8
    #pragma unroll
    for (int i = 0; i < 32; i += 8)
        t[ty + i][tx] = W[(size_t)(k0 + ty + i) * N + n0 + tx];
    __syncthreads();
    #pragma unroll
    for (int i = 0; i < 32; i += 8)
        HiT[(size_t)(n0 + ty + i) * K + k0 + tx] = __float2half_rn(t[tx][ty + i]);
}

// ---------------------------------------------------------------------------
// Shared tile geometry
// ---------------------------------------------------------------------------
#define GBM 128
#define GBN 128
#define GBK 32
#define ASTR 40
#define A_CH (GBM * ASTR)
#define B_CH (GBN * ASTR)

// ---------------------------------------------------------------------------
// fp16x2 GEMM (register-prefetch double buffering):
// C = A @ Wt^T + bias, A = Ah+Al fp16 (exact), W = Wh fp16.
// Output fp32 (Cf32) or exact fp16 hi/lo planes (OH/OL).
// ---------------------------------------------------------------------------
#define F16_SMEM_BYTES ((4 * A_CH + 2 * B_CH) * 2)

__global__ __launch_bounds__(256) void gemm_f16x2(
    const __half* __restrict__ Ah, const __half* __restrict__ Al,
    const __half* __restrict__ Bh,
    const float* __restrict__ bias, float* __restrict__ Cf32,
    __half* __restrict__ OH, __half* __restrict__ OL,
    int M, int N, int K)
{
    extern __shared__ __half smh[];
    uint32_t sbase = smem_u32(smh);

    const int tid  = threadIdx.x;
    const int lane = tid & 31;
    const int wid  = tid >> 5;
    const int wm   = wid >> 2;
    const int wn   = wid & 3;
    const int brow = blockIdx.y;
    const int bcol = blockIdx.x;

    const int lr = tid >> 2;
    const int lc = (tid & 3) * 8;

    const __half* Ah0 = Ah + (size_t)(brow * GBM + lr) * K + lc;
    const __half* Al0 = Al + (size_t)(brow * GBM + lr) * K + lc;
    const __half* Bh0 = Bh + (size_t)(bcol * GBN + lr) * K + lc;
    const size_t rstep = (size_t)64 * K;

    auto aoff = [](int buf, int part) { return (buf * 2 + part) * A_CH; };
    auto boff = [](int buf) { return 4 * A_CH + buf * B_CH; };

    float acc[4][4][4] = {};

    {
        const int so = lr * ASTR + lc;
        *reinterpret_cast<uint4*>(smh + aoff(0,0) + so) = *reinterpret_cast<const uint4*>(Ah0);
        *reinterpret_cast<uint4*>(smh + aoff(0,0) + so + 64*ASTR) = *reinterpret_cast<const uint4*>(Ah0 + rstep);
        *reinterpret_cast<uint4*>(smh + aoff(0,1) + so) = *reinterpret_cast<const uint4*>(Al0);
        *reinterpret_cast<uint4*>(smh + aoff(0,1) + so + 64*ASTR) = *reinterpret_cast<const uint4*>(Al0 + rstep);
        *reinterpret_cast<uint4*>(smh + boff(0) + so) = *reinterpret_cast<const uint4*>(Bh0);
        *reinterpret_cast<uint4*>(smh + boff(0) + so + 64*ASTR) = *reinterpret_cast<const uint4*>(Bh0 + rstep);
    }
    __syncthreads();

    const int nK = K / GBK;
    const int mat = lane >> 3;
    const int r8  = lane & 7;

    int buf = 0;
    for (int kt = 0; kt < nK; kt++) {
        uint4 pf[6];
        const bool more = (kt + 1) < nK;
        if (more) {
            const int ko = (kt + 1) * GBK;
            pf[0] = *reinterpret_cast<const uint4*>(Ah0 + ko);
            pf[1] = *reinterpret_cast<const uint4*>(Ah0 + ko + rstep);
            pf[2] = *reinterpret_cast<const uint4*>(Al0 + ko);
            pf[3] = *reinterpret_cast<const uint4*>(Al0 + ko + rstep);
            pf[4] = *reinterpret_cast<const uint4*>(Bh0 + ko);
            pf[5] = *reinterpret_cast<const uint4*>(Bh0 + ko + rstep);
        }

        #pragma unroll
        for (int ks = 0; ks < 2; ks++) {
            uint32_t ah[4][4], al[4][4], bh[4][2];
            #pragma unroll
            for (int mi = 0; mi < 4; mi++) {
                const int row = wm * 64 + mi * 16 + (mat & 1) * 8 + r8;
                const int col = ks * 16 + (mat >> 1) * 8;
                const uint32_t a_addr = sbase + (uint32_t)(aoff(buf,0) + row * ASTR + col) * 2;
                ldsm4(ah[mi][0], ah[mi][1], ah[mi][2], ah[mi][3], a_addr);
                ldsm4(al[mi][0], al[mi][1], al[mi][2], al[mi][3], a_addr + A_CH * 2);
            }
            #pragma unroll
            for (int nt = 0; nt < 2; nt++) {
                const int row = wn * 32 + nt * 16 + (mat >> 1) * 8 + r8;
                const int col = ks * 16 + (mat & 1) * 8;
                const uint32_t b_addr = sbase + (uint32_t)(boff(buf) + row * ASTR + col) * 2;
                uint32_t r0, r1, r2, r3;
                ldsm4(r0, r1, r2, r3, b_addr);
                bh[2*nt][0] = r0; bh[2*nt][1] = r1; bh[2*nt+1][0] = r2; bh[2*nt+1][1] = r3;
            }
            #pragma unroll
            for (int mi = 0; mi < 4; mi++) {
                #pragma unroll
                for (int nj = 0; nj < 4; nj++)
                    mma_f16(acc[mi][nj], ah[mi], bh[nj]);
                #pragma unroll
                for (int nj = 0; nj < 4; nj++)
                    mma_f16(acc[mi][nj], al[mi], bh[nj]);
            }
        }

        if (more) {
            const int nb = buf ^ 1;
            const int so = lr * ASTR + lc;
            *reinterpret_cast<uint4*>(smh + aoff(nb,0) + so)           = pf[0];
            *reinterpret_cast<uint4*>(smh + aoff(nb,0) + so + 64*ASTR) = pf[1];
            *reinterpret_cast<uint4*>(smh + aoff(nb,1) + so)           = pf[2];
            *reinterpret_cast<uint4*>(smh + aoff(nb,1) + so + 64*ASTR) = pf[3];
            *reinterpret_cast<uint4*>(smh + boff(nb) + so)             = pf[4];
            *reinterpret_cast<uint4*>(smh + boff(nb) + so + 64*ASTR)   = pf[5];
            __syncthreads();
        }
        buf ^= 1;
    }

    #pragma unroll
    for (int nj = 0; nj < 4; nj++) {
        const int c = bcol * GBN + wn * 32 + nj * 8 + (lane & 3) * 2;
        const float2 bv = *reinterpret_cast<const float2*>(bias + c);
        #pragma unroll
        for (int mi = 0; mi < 4; mi++) {
            const int r0 = brow * GBM + wm * 64 + mi * 16 + (lane >> 2);
            float2 o0, o1;
            o0.x = acc[mi][nj][0] + bv.x;  o0.y = acc[mi][nj][1] + bv.y;
            o1.x = acc[mi][nj][2] + bv.x;  o1.y = acc[mi][nj][3] + bv.y;
            if (Cf32) {
                *reinterpret_cast<float2*>(Cf32 + (size_t)r0 * N + c)       = o0;
                *reinterpret_cast<float2*>(Cf32 + (size_t)(r0 + 8) * N + c) = o1;
            } else {
                uint32_t h0, l0, h1, l1;
                split_pair_f16(o0.x, o0.y, h0, l0);
                split_pair_f16(o1.x, o1.y, h1, l1);
                const size_t e0 = (size_t)r0 * N + c;
                const size_t e1 = (size_t)(r0 + 8) * N + c;
                *reinterpret_cast<uint32_t*>(OH + e0) = h0;
                *reinterpret_cast<uint32_t*>(OL + e0) = l0;
                *reinterpret_cast<uint32_t*>(OH + e1) = h1;
                *reinterpret_cast<uint32_t*>(OL + e1) = l1;
            }
        }
    }
}

// ---------------------------------------------------------------------------
// fp16 sparse-causal attention, register-resident P, K/V hi-plane only.
// QK: (Qh+Ql)·Kh (2 mmas) — error Q·Kl ~ 2^-11 of score.
// PV: (Ph+Pl)·Vh (2 mmas) — P split exact; error P·Vl ~ 2^-11 of O.
// smem (fp16 elems): Qh@0 Ql@9216 Kh@18432 Vh@36864; total 55296 = 110.6 KB.
// ---------------------------------------------------------------------------
#define AT_QSTR 72
#define AT_KSTR 72
#define AT_QH   0
#define AT_QL   9216
#define AT_KH   18432
#define AT_VH   36864
#define AT_SMEM_BYTES (55296 * 2 + 256)

__device__ __forceinline__ int key_map(int j, int nstr, int qb) {
    return (j < nstr) ? ((j >> 3) << 7) + (STRIDE_BLK - CKEEP) + (j & 7)
                      : (qb << 7) + (j - nstr);
}

__global__ __launch_bounds__(256, 1) void attn_tc(
    const __half* __restrict__ QKVH, const __half* __restrict__ QKVL,
    __half* __restrict__ OH, __half* __restrict__ OL)
{
    const int qb  = 15 - blockIdx.x;
    const int h   = blockIdx.y;
    const int b   = blockIdx.z;
    const int tid = threadIdx.x;
    const int lane = tid & 31;
    const int wid  = tid >> 5;
    const int nstr = qb * CKEEP;
    const int cnt  = nstr + 128;
    const int gmax = (cnt + 15) >> 4;
    const int q0   = qb * 128;

    extern __shared__ __half sh16[];
    const uint32_t sbase = smem_u32(sh16);

    const size_t base = (size_t)b * SEQ * (3 * EMB);

    // --- stage Q hi/lo ---
    {
        const int row = tid >> 1;
        const int d0  = (tid & 1) * 32;
        const size_t g = base + (size_t)(q0 + row) * (3 * EMB) + h * HDIM + d0;
        const int eo = row * AT_QSTR + d0;
        #pragma unroll
        for (int i = 0; i < 4; i++) {
            *reinterpret_cast<uint4*>(sh16 + AT_QH + eo + i * 8) =
                *reinterpret_cast<const uint4*>(QKVH + g + i * 8);
            *reinterpret_cast<uint4*>(sh16 + AT_QL + eo + i * 8) =
                *reinterpret_cast<const uint4*>(QKVL + g + i * 8);
        }
    }

    // --- stage K hi and V hi row-major (thread j = key slot) ---
    {
        const int j = tid;
        if (j < cnt) {
            const int key = key_map(j, nstr, qb);
            const size_t gk = base + (size_t)key * (3 * EMB) + EMB + h * HDIM;
            const size_t gv = gk + EMB;
            const int eo = j * AT_KSTR;
            #pragma unroll
            for (int i = 0; i < 8; i++) {
                *reinterpret_cast<uint4*>(sh16 + AT_KH + eo + i * 8) =
                    *reinterpret_cast<const uint4*>(QKVH + gk + i * 8);
                *reinterpret_cast<uint4*>(sh16 + AT_VH + eo + i * 8) =
                    *reinterpret_cast<const uint4*>(QKVH + gv + i * 8);
            }
        } else if (j < 16 * gmax) {
            const uint4 z = {0u, 0u, 0u, 0u};
            const int eo = j * AT_KSTR;
            #pragma unroll
            for (int i = 0; i < 8; i++) {
                *reinterpret_cast<uint4*>(sh16 + AT_KH + eo + i * 8) = z;
                *reinterpret_cast<uint4*>(sh16 + AT_VH + eo + i * 8) = z;
            }
        }
    }
    __syncthreads();

    const int mat = lane >> 3;
    const int r8  = lane & 7;

    // --- scores: (Qh+Ql) x Kh ---
    float sacc[32][4];
    #pragma unroll
    for (int t = 0; t < 32; t++)
        #pragma unroll
        for (int e = 0; e < 4; e++) sacc[t][e] = 0.f;

    {
        const int arow = wid * 16 + (mat & 1) * 8 + r8;
        #pragma unroll
        for (int ks = 0; ks < 4; ks++) {
            uint32_t ah[4], al[4];
            const uint32_t aaddr = sbase + (uint32_t)(AT_QH + arow * AT_QSTR + ks * 16 + (mat >> 1) * 8) * 2;
            ldsm4(ah[0], ah[1], ah[2], ah[3], aaddr);
            ldsm4(al[0], al[1], al[2], al[3], aaddr + (AT_QL - AT_QH) * 2);
            #pragma unroll
            for (int g = 0; g < 16; g++) {
                if (g < gmax) {
                    const int brow = g * 16 + (mat >> 1) * 8 + r8;
                    const uint32_t baddr = sbase + (uint32_t)(AT_KH + brow * AT_KSTR + ks * 16 + (mat & 1) * 8) * 2;
                    uint32_t bh[2][2];
                    uint32_t r0, r1, r2, r3;
                    ldsm4(r0, r1, r2, r3, baddr);
                    bh[0][0] = r0; bh[0][1] = r1; bh[1][0] = r2; bh[1][1] = r3;
                    mma_f16(sacc[2 * g],     ah, bh[0]);
                    mma_f16(sacc[2 * g + 1], ah, bh[1]);
                    mma_f16(sacc[2 * g],     al, bh[0]);
                    mma_f16(sacc[2 * g + 1], al, bh[1]);
                }
            }
        }
    }

    // --- in-register masked softmax ---
    const int r0   = lane >> 2;
    const int c0   = (lane & 3) * 2;
    const int rowA = wid * 16 + r0;
    const int rowB = rowA + 8;
    const int limA = nstr + rowA;
    const int limB = nstr + rowB;
    const float scale = 0.125f;

    float mA = -1e30f, mB = -1e30f;
    #pragma unroll
    for (int t = 0; t < 32; t++) {
        if (t < 2 * gmax) {
            const int c = t * 8 + c0;
            sacc[t][0] = (c     <= limA) ? sacc[t][0] * scale : -1e30f;
            sacc[t][1] = (c + 1 <= limA) ? sacc[t][1] * scale : -1e30f;
            sacc[t][2] = (c     <= limB) ? sacc[t][2] * scale : -1e30f;
            sacc[t][3] = (c + 1 <= limB) ? sacc[t][3] * scale : -1e30f;
            mA = fmaxf(mA, fmaxf(sacc[t][0], sacc[t][1]));
            mB = fmaxf(mB, fmaxf(sacc[t][2], sacc[t][3]));
        }
    }
    mA = fmaxf(mA, __shfl_xor_sync(0xffffffffu, mA, 1));
    mA = fmaxf(mA, __shfl_xor_sync(0xffffffffu, mA, 2));
    mB = fmaxf(mB, __shfl_xor_sync(0xffffffffu, mB, 1));
    mB = fmaxf(mB, __shfl_xor_sync(0xffffffffu, mB, 2));

    float sA = 0.f, sB = 0.f;
    #pragma unroll
    for (int t = 0; t < 32; t++) {
        if (t < 2 * gmax) {
            sacc[t][0] = __expf(sacc[t][0] - mA);
            sacc[t][1] = __expf(sacc[t][1] - mA);
            sacc[t][2] = __expf(sacc[t][2] - mB);
            sacc[t][3] = __expf(sacc[t][3] - mB);
            sA += sacc[t][0] + sacc[t][1];
            sB += sacc[t][2] + sacc[t][3];
        }
    }
    sA += __shfl_xor_sync(0xffffffffu, sA, 1);
    sA += __shfl_xor_sync(0xffffffffu, sA, 2);
    sB += __shfl_xor_sync(0xffffffffu, sB, 1);
    sB += __shfl_xor_sync(0xffffffffu, sB, 2);

    // --- O = P @ V: (Ph+Pl) x Vh, V transposed at load ---
    float pacc[8][4];
    #pragma unroll
    for (int t = 0; t < 8; t++)
        #pragma unroll
        for (int e = 0; e < 4; e++) pacc[t][e] = 0.f;

    #pragma unroll
    for (int ks = 0; ks < 16; ks++) {
        if (ks < gmax) {
            uint32_t ah[4], al[4];
            split_pair_f16(sacc[2*ks][0],   sacc[2*ks][1],   ah[0], al[0]);
            split_pair_f16(sacc[2*ks][2],   sacc[2*ks][3],   ah[1], al[1]);
            split_pair_f16(sacc[2*ks+1][0], sacc[2*ks+1][1], ah[2], al[2]);
            split_pair_f16(sacc[2*ks+1][2], sacc[2*ks+1][3], ah[3], al[3]);
            const int vkrow = ks * 16 + (mat & 1) * 8 + r8;
            #pragma unroll
            for (int g = 0; g < 4; g++) {
                const uint32_t baddr = sbase + (uint32_t)(AT_VH + vkrow * AT_KSTR + g * 16 + (mat >> 1) * 8) * 2;
                uint32_t bh[2][2];
                uint32_t r0_, r1_, r2_, r3_;
                ldsm4t(r0_, r1_, r2_, r3_, baddr);
                bh[0][0] = r0_; bh[0][1] = r1_; bh[1][0] = r2_; bh[1][1] = r3_;
                mma_f16(pacc[2 * g],     ah, bh[0]);
                mma_f16(pacc[2 * g + 1], ah, bh[1]);
                mma_f16(pacc[2 * g],     al, bh[0]);
                mma_f16(pacc[2 * g + 1], al, bh[1]);
            }
        }
    }

    // --- epilogue: normalize, exact fp16 hi/lo split for proj GEMM ---
    {
        const float invA = 1.0f / sA;
        const float invB = 1.0f / sB;
        const size_t oA = (size_t)(b * SEQ + q0 + rowA) * EMB + h * HDIM;
        const size_t oB = (size_t)(b * SEQ + q0 + rowB) * EMB + h * HDIM;
        #pragma unroll
        for (int t = 0; t < 8; t++) {
            const int d = t * 8 + c0;
            uint32_t hA, lA, hB, lB;
            split_pair_f16(pacc[t][0] * invA, pacc[t][1] * invA, hA, lA);
            split_pair_f16(pacc[t][2] * invB, pacc[t][3] * invB, hB, lB);
            *reinterpret_cast<uint32_t*>(OH + oA + d) = hA;
            *reinterpret_cast<uint32_t*>(OL + oA + d) = lA;
            *reinterpret_cast<uint32_t*>(OH + oB + d) = hB;
            *reinterpret_cast<uint32_t*>(OL + oB + d) = lB;
        }
    }
}

// ---------------------------------------------------------------------------
extern "C" void kernel_launch(void* const* d_in, const int* in_sizes, int n_in,
                              void* d_out, int out_size) {
    const float* hs     = (const float*)d_in[0];
    const float* W_attn = (const float*)d_in[1];
    const float* b_attn = (const float*)d_in[2];
    const float* W_proj = (const float*)d_in[3];
    const float* b_proj = (const float*)d_in[4];
    float* out = (float*)d_out;

    __half *QKVH, *QKVL, *AH, *AL, *WH, *WP;
    cudaGetSymbolAddress((void**)&QKVH, g_QKVH);
    cudaGetSymbolAddress((void**)&QKVL, g_QKVL);
    cudaGetSymbolAddress((void**)&AH, g_AH);
    cudaGetSymbolAddress((void**)&AL, g_AL);
    cudaGetSymbolAddress((void**)&WH, g_WH);
    cudaGetSymbolAddress((void**)&WP, g_WP);

    static bool attr_set = false;
    if (!attr_set) {
        cudaFuncSetAttribute(gemm_f16x2,
                             cudaFuncAttributeMaxDynamicSharedMemorySize,
                             F16_SMEM_BYTES);
        cudaFuncSetAttribute(attn_tc,
                             cudaFuncAttributeMaxDynamicSharedMemorySize,
                             AT_SMEM_BYTES);
        attr_set = true;
    }

    const int M = BATCH * SEQ;  // 4096
    const int K = EMB;          // 1024

    // 1) hs -> fp16 hi/lo planes; both W transposes in one launch
    conv_split_f16<<<(M * K / 4 + 255) / 256, 256>>>(hs, AH, AL, M * K / 4);
    {
        dim3 g(3 * EMB / 32, EMB / 32, 2), t(32, 8);
        conv_T_f16h_dual<<<g, t>>>(W_attn, WH, 3 * EMB, W_proj, WP, EMB, K);
    }
    // 2) QKV projection: fp16x2 -> exact fp16 hi/lo planes
    {
        dim3 grid((3 * EMB) / GBN, M / GBM);
        gemm_f16x2<<<grid, 256, F16_SMEM_BYTES>>>(
            AH, AL, WH, b_attn, nullptr, QKVH, QKVL, M, 3 * EMB, K);
    }
    // 3) Sparse attention (fp16, hi-plane K/V) -> exact fp16 planes into AH/AL
    {
        dim3 grid(16, NHEAD, BATCH);
        attn_tc<<<grid, 256, AT_SMEM_BYTES>>>(QKVH, QKVL, AH, AL);
    }
    // 4) Output projection fp16x2 (fp32 out)
    {
        dim3 grid(EMB / GBN, M / GBM);
        gemm_f16x2<<<grid, 256, F16_SMEM_BYTES>>>(
            AH, AL, WP, b_proj, out, nullptr, nullptr, M, EMB, K);
    }
}